// round 1
// baseline (speedup 1.0000x reference)
#include <cuda_runtime.h>
#include <cuda_bf16.h>
#include <math.h>

// Problem constants
#define BATCH 2
#define SLEN 2048
#define HID 4096
#define NHEAD 32
#define HDIM 128
#define MROWS (BATCH * SLEN)       // 4096
#define QKV_N (3 * HID)            // 12288

// ---------------- scratch (no allocations allowed) ----------------
__device__ float g_qkv[(size_t)MROWS * QKV_N];   // 4096 x 12288 (201 MB)
__device__ float g_ctx[(size_t)MROWS * HID];     // 4096 x 4096  (67 MB)

// ---------------- tiled fp32 SGEMM: C = A[MxK] * B[KxN] (+bias) ----------------
// 128x128 tile, TK=8, 256 threads, 8x8 per thread.
__global__ __launch_bounds__(256, 2)
void sgemm_kernel(const float* __restrict__ A, const float* __restrict__ Bm,
                  const float* __restrict__ bias, float* __restrict__ C,
                  int M, int N, int K)
{
    __shared__ float As[8 * 128];   // As[k][m]
    __shared__ float Bs[8 * 128];   // Bs[k][n]

    const int tid = threadIdx.x;
    const int ty = tid >> 4;        // 0..15 -> rows
    const int tx = tid & 15;        // 0..15 -> cols
    const int m0 = blockIdx.y * 128;
    const int n0 = blockIdx.x * 128;

    const int arow = tid >> 1;      // 0..127
    const int aseg = tid & 1;       // 0..1 (x4 floats)
    const int brow = tid >> 5;      // 0..7
    const int bseg = tid & 31;      // 0..31 (x4 floats)

    float acc[8][8];
#pragma unroll
    for (int i = 0; i < 8; i++)
#pragma unroll
        for (int j = 0; j < 8; j++) acc[i][j] = 0.f;

    for (int k0 = 0; k0 < K; k0 += 8) {
        float4 av = *(const float4*)(A + (size_t)(m0 + arow) * K + k0 + aseg * 4);
        float4 bv = *(const float4*)(Bm + (size_t)(k0 + brow) * N + n0 + bseg * 4);
        __syncthreads();   // previous compute done before overwriting smem
        As[(aseg * 4 + 0) * 128 + arow] = av.x;
        As[(aseg * 4 + 1) * 128 + arow] = av.y;
        As[(aseg * 4 + 2) * 128 + arow] = av.z;
        As[(aseg * 4 + 3) * 128 + arow] = av.w;
        *(float4*)(Bs + brow * 128 + bseg * 4) = bv;
        __syncthreads();

#pragma unroll
        for (int kk = 0; kk < 8; kk++) {
            float ra[8], rb[8];
#pragma unroll
            for (int i = 0; i < 8; i++) ra[i] = As[kk * 128 + ty * 8 + i];
#pragma unroll
            for (int j = 0; j < 8; j++) rb[j] = Bs[kk * 128 + tx * 8 + j];
#pragma unroll
            for (int i = 0; i < 8; i++)
#pragma unroll
                for (int j = 0; j < 8; j++) acc[i][j] = fmaf(ra[i], rb[j], acc[i][j]);
        }
    }

#pragma unroll
    for (int i = 0; i < 8; i++) {
        const int m = m0 + ty * 8 + i;
#pragma unroll
        for (int j = 0; j < 8; j++) {
            const int n = n0 + tx * 8 + j;
            float v = acc[i][j];
            if (bias) v += bias[n];
            C[(size_t)m * N + n] = v;
        }
    }
}

// ---------------- RoPE on q and k sections of qkv ----------------
// one thread per (row, head, pair-index); handles both q and k.
__global__ void rope_kernel(float* __restrict__ qkv, const int* __restrict__ positions)
{
    int idx = blockIdx.x * blockDim.x + threadIdx.x;   // MROWS * NHEAD * 64
    if (idx >= MROWS * NHEAD * 64) return;
    const int i = idx & 63;            // pair index 0..63
    const int h = (idx >> 6) & 31;     // head
    const int m = idx >> 11;           // row 0..4095

    const float pos = (float)positions[m];
    const float inv_freq = powf(10000.0f, -(float)i / 64.0f);   // base^{-2i/128}
    const float ang = pos * inv_freq;
    const float c = cosf(ang);
    const float s = sinf(ang);

    // q section
    float* qp = qkv + (size_t)m * QKV_N + h * HDIM + i;
    float x1 = qp[0], x2 = qp[64];
    qp[0]  = x1 * c - x2 * s;
    qp[64] = x2 * c + x1 * s;
    // k section
    float* kp = qp + HID;
    x1 = kp[0]; x2 = kp[64];
    kp[0]  = x1 * c - x2 * s;
    kp[64] = x2 * c + x1 * s;
}

// ---------------- flash attention (fp32, causal) ----------------
// grid (qt=32, h=32, b=2); 256 threads; q-tile 64, k-tile 64.
#define QTS 64
#define KTS 64
#define TSTRIDE 132               // padded row stride for Q/K/V tiles
#define PSTRIDE 65                // padded row stride for score tile
#define FLASH_SMEM_FLOATS (QTS*TSTRIDE + KTS*TSTRIDE + QTS*PSTRIDE + 3*QTS)
#define FLASH_SMEM_BYTES (FLASH_SMEM_FLOATS * 4)

__global__ __launch_bounds__(256, 2)
void flash_kernel(const float* __restrict__ qkv, float* __restrict__ ctx)
{
    const int qt = blockIdx.x;
    const int h  = blockIdx.y;
    const int b  = blockIdx.z;

    extern __shared__ float sm[];
    float* Qs   = sm;                       // 64 x 132
    float* KVs  = Qs + QTS * TSTRIDE;       // 64 x 132 (K then reused for V)
    float* sP   = KVs + KTS * TSTRIDE;      // 64 x 65
    float* mrow = sP + QTS * PSTRIDE;       // 64
    float* lrow = mrow + QTS;               // 64
    float* arow = lrow + QTS;               // 64

    const int tid = threadIdx.x;
    const int ty = tid >> 4;     // 0..15
    const int tx = tid & 15;     // 0..15
    const float scale = 0.08838834764831845f;   // 1/sqrt(128)

    // load Q tile (64 x 128)
    const float* qbase = qkv + (size_t)(b * SLEN + qt * QTS) * QKV_N + h * HDIM;
    for (int i = tid; i < QTS * HDIM / 4; i += 256) {
        const int row = i >> 5;          // /32 float4 per row
        const int c4  = i & 31;
        float4 v = *(const float4*)(qbase + (size_t)row * QKV_N + c4 * 4);
        float* dst = Qs + row * TSTRIDE + c4 * 4;
        dst[0] = v.x; dst[1] = v.y; dst[2] = v.z; dst[3] = v.w;
    }
    if (tid < QTS) { mrow[tid] = -INFINITY; lrow[tid] = 0.f; }

    float acc[4][8];
#pragma unroll
    for (int i = 0; i < 4; i++)
#pragma unroll
        for (int j = 0; j < 8; j++) acc[i][j] = 0.f;

    for (int kt = 0; kt <= qt; kt++) {
        const float* kbase = qkv + (size_t)(b * SLEN + kt * KTS) * QKV_N + HID + h * HDIM;
        __syncthreads();   // previous PV done with KVs
        for (int i = tid; i < KTS * HDIM / 4; i += 256) {
            const int row = i >> 5;
            const int c4  = i & 31;
            float4 v = *(const float4*)(kbase + (size_t)row * QKV_N + c4 * 4);
            float* dst = KVs + row * TSTRIDE + c4 * 4;
            dst[0] = v.x; dst[1] = v.y; dst[2] = v.z; dst[3] = v.w;
        }
        __syncthreads();

        // scores: 4 rows x 4 cols per thread
        float sc[4][4];
#pragma unroll
        for (int i = 0; i < 4; i++)
#pragma unroll
            for (int j = 0; j < 4; j++) sc[i][j] = 0.f;

#pragma unroll 4
        for (int d = 0; d < HDIM; d++) {
            float qa[4], kb[4];
#pragma unroll
            for (int i = 0; i < 4; i++) qa[i] = Qs[(ty * 4 + i) * TSTRIDE + d];
#pragma unroll
            for (int j = 0; j < 4; j++) kb[j] = KVs[(tx * 4 + j) * TSTRIDE + d];
#pragma unroll
            for (int i = 0; i < 4; i++)
#pragma unroll
                for (int j = 0; j < 4; j++) sc[i][j] = fmaf(qa[i], kb[j], sc[i][j]);
        }

        const int qrow0 = qt * QTS + ty * 4;
        const int kcol0 = kt * KTS + tx * 4;
#pragma unroll
        for (int i = 0; i < 4; i++)
#pragma unroll
            for (int j = 0; j < 4; j++) {
                float s = sc[i][j] * scale;
                if (kt == qt && (kcol0 + j) > (qrow0 + i)) s = -INFINITY;
                sP[(ty * 4 + i) * PSTRIDE + tx * 4 + j] = s;
            }
        __syncthreads();   // scores written, KVs free

        // load V tile into KVs (all threads)
        const float* vbase = kbase + HID;
        for (int i = tid; i < KTS * HDIM / 4; i += 256) {
            const int row = i >> 5;
            const int c4  = i & 31;
            float4 v = *(const float4*)(vbase + (size_t)row * QKV_N + c4 * 4);
            float* dst = KVs + row * TSTRIDE + c4 * 4;
            dst[0] = v.x; dst[1] = v.y; dst[2] = v.z; dst[3] = v.w;
        }

        // online softmax per row (threads 0..63)
        if (tid < QTS) {
            const int r = tid;
            float m_old = mrow[r];
            float m_new = m_old;
            for (int c = 0; c < KTS; c++) m_new = fmaxf(m_new, sP[r * PSTRIDE + c]);
            const float al = expf(m_old - m_new);
            float lsum = 0.f;
            for (int c = 0; c < KTS; c++) {
                float p = expf(sP[r * PSTRIDE + c] - m_new);
                sP[r * PSTRIDE + c] = p;
                lsum += p;
            }
            mrow[r] = m_new;
            lrow[r] = lrow[r] * al + lsum;
            arow[r] = al;
        }
        __syncthreads();   // V loaded + softmax done

        // rescale accumulators and add P*V ; cols tx*8..tx*8+7
#pragma unroll
        for (int i = 0; i < 4; i++) {
            const float al = arow[ty * 4 + i];
#pragma unroll
            for (int j = 0; j < 8; j++) acc[i][j] *= al;
        }
#pragma unroll 4
        for (int c = 0; c < KTS; c++) {
            float p[4];
#pragma unroll
            for (int i = 0; i < 4; i++) p[i] = sP[(ty * 4 + i) * PSTRIDE + c];
            float4 v0 = *(const float4*)(KVs + c * TSTRIDE + tx * 8);
            float4 v1 = *(const float4*)(KVs + c * TSTRIDE + tx * 8 + 4);
#pragma unroll
            for (int i = 0; i < 4; i++) {
                acc[i][0] = fmaf(p[i], v0.x, acc[i][0]);
                acc[i][1] = fmaf(p[i], v0.y, acc[i][1]);
                acc[i][2] = fmaf(p[i], v0.z, acc[i][2]);
                acc[i][3] = fmaf(p[i], v0.w, acc[i][3]);
                acc[i][4] = fmaf(p[i], v1.x, acc[i][4]);
                acc[i][5] = fmaf(p[i], v1.y, acc[i][5]);
                acc[i][6] = fmaf(p[i], v1.z, acc[i][6]);
                acc[i][7] = fmaf(p[i], v1.w, acc[i][7]);
            }
        }
    }

    // epilogue: out = acc / l
    float* obase = ctx + (size_t)(b * SLEN + qt * QTS) * HID + h * HDIM;
#pragma unroll
    for (int i = 0; i < 4; i++) {
        const int r = ty * 4 + i;
        const float inv = 1.0f / lrow[r];
#pragma unroll
        for (int j = 0; j < 8; j++)
            obase[(size_t)r * HID + tx * 8 + j] = acc[i][j] * inv;
    }
}

// ---------------- launch ----------------
extern "C" void kernel_launch(void* const* d_in, const int* in_sizes, int n_in,
                              void* d_out, int out_size)
{
    const float* hs    = (const float*)d_in[0];   // (B,S,4096) f32
    const int*   pos   = (const int*)d_in[1];     // (B,S) i32
    const float* Wqkv  = (const float*)d_in[2];   // (4096,12288) f32
    const float* bqkv  = (const float*)d_in[3];   // (12288,) f32
    const float* Wo    = (const float*)d_in[4];   // (4096,4096) f32
    float* out = (float*)d_out;                   // (B,S,4096) f32

    float *qkv, *ctx;
    cudaGetSymbolAddress((void**)&qkv, g_qkv);
    cudaGetSymbolAddress((void**)&ctx, g_ctx);

    // 1) qkv = hs @ W_qkv + b
    {
        dim3 grid(QKV_N / 128, MROWS / 128);   // (96, 32)
        sgemm_kernel<<<grid, 256>>>(hs, Wqkv, bqkv, qkv, MROWS, QKV_N, HID);
    }
    // 2) RoPE (q and k in-place)
    {
        int total = MROWS * NHEAD * 64;
        rope_kernel<<<(total + 255) / 256, 256>>>(qkv, pos);
    }
    // 3) causal flash attention -> ctx
    {
        cudaFuncSetAttribute(flash_kernel, cudaFuncAttributeMaxDynamicSharedMemorySize,
                             FLASH_SMEM_BYTES);
        dim3 grid(SLEN / QTS, NHEAD, BATCH);   // (32, 32, 2)
        flash_kernel<<<grid, 256, FLASH_SMEM_BYTES>>>(qkv, ctx);
    }
    // 4) out = ctx @ W_o
    {
        dim3 grid(HID / 128, MROWS / 128);     // (32, 32)
        sgemm_kernel<<<grid, 256>>>(ctx, Wo, nullptr, out, MROWS, HID, HID);
    }
}

// round 3
// speedup vs baseline: 1.3678x; 1.3678x over previous
#include <cuda_runtime.h>
#include <cuda_bf16.h>
#include <math.h>

// Problem constants
#define BATCH 2
#define SLEN 2048
#define HID 4096
#define NHEAD 32
#define HDIM 128
#define MROWS (BATCH * SLEN)       // 4096
#define QKV_N (3 * HID)            // 12288

// ---------------- scratch (no allocations allowed) ----------------
__device__ float g_qkv[(size_t)MROWS * QKV_N];   // 4096 x 12288 (201 MB)
__device__ float g_ctx[(size_t)MROWS * HID];     // 4096 x 4096  (67 MB)

// ================= 3xTF32 tensor-core GEMM =================
// C[MxN] = A[MxK] * B[KxN] (+bias), fp32 storage, tf32 MMA with hi/lo
// error compensation (a_hi*b_hi + a_hi*b_lo + a_lo*b_hi).
#define BM 128
#define BN 128
#define BK 32
#define ASTRIDE 36     // 32 + 4 pad
#define BSTRIDE 136    // 128 + 8 pad
#define STAGE_FLOATS (BM * ASTRIDE + BK * BSTRIDE)    // 8960
#define GEMM_SMEM_BYTES (2 * STAGE_FLOATS * 4)        // 71680

#define CP_ASYNC16(dst, src) \
    asm volatile("cp.async.cg.shared.global [%0], [%1], 16;\n" :: "r"(dst), "l"(src))
#define CP_COMMIT() asm volatile("cp.async.commit_group;\n" ::: "memory")
#define CP_WAIT(n)  asm volatile("cp.async.wait_group %0;\n" :: "n"(n) : "memory")

__device__ __forceinline__ unsigned f2tf32(float x)
{
    unsigned r;
    asm("cvt.rna.tf32.f32 %0, %1;" : "=r"(r) : "f"(x));
    return r;
}

__device__ __forceinline__ void mma_tf32(float* c, const unsigned* a, const unsigned* b)
{
    asm volatile(
        "mma.sync.aligned.m16n8k8.row.col.f32.tf32.tf32.f32 "
        "{%0,%1,%2,%3},{%4,%5,%6,%7},{%8,%9},{%0,%1,%2,%3};"
        : "+f"(c[0]), "+f"(c[1]), "+f"(c[2]), "+f"(c[3])
        : "r"(a[0]), "r"(a[1]), "r"(a[2]), "r"(a[3]), "r"(b[0]), "r"(b[1]));
}

__global__ __launch_bounds__(256)
void gemm_tf32_kernel(const float* __restrict__ A, const float* __restrict__ Bm,
                      const float* __restrict__ bias, float* __restrict__ C,
                      int M, int N, int K)
{
    extern __shared__ float sm[];
    const int tid = threadIdx.x;
    const int wid = tid >> 5;
    const int lane = tid & 31;
    const int grp = lane >> 2;     // 0..7
    const int qid = lane & 3;      // 0..3
    const int warp_m = wid >> 2;   // 0..1  (64 rows each)
    const int warp_n = wid & 3;    // 0..3  (32 cols each)

    const int m0 = blockIdx.y * BM;
    const int n0 = blockIdx.x * BN;

    float acc[4][4][4];
#pragma unroll
    for (int i = 0; i < 4; i++)
#pragma unroll
        for (int j = 0; j < 4; j++)
#pragma unroll
            for (int r = 0; r < 4; r++) acc[i][j][r] = 0.f;

    unsigned smem_base;
    {
        unsigned long long gp = __cvta_generic_to_shared(sm);
        smem_base = (unsigned)gp;
    }

    const int NIT = K / BK;

    auto load_stage = [&](int stage, int k0) {
        unsigned sa = smem_base + (unsigned)(stage * STAGE_FLOATS) * 4u;
        unsigned sb = sa + (unsigned)(BM * ASTRIDE) * 4u;
#pragma unroll
        for (int p = 0; p < 4; p++) {
            int i = p * 256 + tid;
            int row = i >> 3;              // 0..127
            int seg = i & 7;               // 0..7 (x4 floats)
            const float* g = A + (size_t)(m0 + row) * K + k0 + seg * 4;
            CP_ASYNC16(sa + (unsigned)(row * ASTRIDE + seg * 4) * 4u, g);
        }
#pragma unroll
        for (int p = 0; p < 4; p++) {
            int i = p * 256 + tid;
            int row = i >> 5;              // 0..31
            int seg = i & 31;              // 0..31 (x4 floats)
            const float* g = Bm + (size_t)(k0 + row) * N + n0 + seg * 4;
            CP_ASYNC16(sb + (unsigned)(row * BSTRIDE + seg * 4) * 4u, g);
        }
    };

    load_stage(0, 0);
    CP_COMMIT();

    int stage = 0;
    for (int it = 0; it < NIT; it++) {
        if (it + 1 < NIT) {
            load_stage(stage ^ 1, (it + 1) * BK);
            CP_COMMIT();
            CP_WAIT(1);
        } else {
            CP_WAIT(0);
        }
        __syncthreads();

        const float* As = sm + stage * STAGE_FLOATS;
        const float* Bs = As + BM * ASTRIDE;

#pragma unroll
        for (int kk = 0; kk < 4; kk++) {
            unsigned ahi[4][4], alo[4][4], bhi[4][2], blo[4][2];
#pragma unroll
            for (int mt = 0; mt < 4; mt++) {
                const float* p = As + (warp_m * 64 + mt * 16 + grp) * ASTRIDE + kk * 8 + qid;
                float v0 = p[0];
                float v1 = p[8 * ASTRIDE];
                float v2 = p[4];
                float v3 = p[8 * ASTRIDE + 4];
                ahi[mt][0] = f2tf32(v0); alo[mt][0] = f2tf32(v0 - __uint_as_float(ahi[mt][0]));
                ahi[mt][1] = f2tf32(v1); alo[mt][1] = f2tf32(v1 - __uint_as_float(ahi[mt][1]));
                ahi[mt][2] = f2tf32(v2); alo[mt][2] = f2tf32(v2 - __uint_as_float(ahi[mt][2]));
                ahi[mt][3] = f2tf32(v3); alo[mt][3] = f2tf32(v3 - __uint_as_float(ahi[mt][3]));
            }
#pragma unroll
            for (int nt = 0; nt < 4; nt++) {
                const float* p = Bs + (kk * 8 + qid) * BSTRIDE + warp_n * 32 + nt * 8 + grp;
                float v0 = p[0];
                float v1 = p[4 * BSTRIDE];
                bhi[nt][0] = f2tf32(v0); blo[nt][0] = f2tf32(v0 - __uint_as_float(bhi[nt][0]));
                bhi[nt][1] = f2tf32(v1); blo[nt][1] = f2tf32(v1 - __uint_as_float(bhi[nt][1]));
            }
            // correction terms first, then main term
#pragma unroll
            for (int mt = 0; mt < 4; mt++)
#pragma unroll
                for (int nt = 0; nt < 4; nt++)
                    mma_tf32(acc[mt][nt], alo[mt], bhi[nt]);
#pragma unroll
            for (int mt = 0; mt < 4; mt++)
#pragma unroll
                for (int nt = 0; nt < 4; nt++)
                    mma_tf32(acc[mt][nt], ahi[mt], blo[nt]);
#pragma unroll
            for (int mt = 0; mt < 4; mt++)
#pragma unroll
                for (int nt = 0; nt < 4; nt++)
                    mma_tf32(acc[mt][nt], ahi[mt], bhi[nt]);
        }
        __syncthreads();
        stage ^= 1;
    }

#pragma unroll
    for (int mt = 0; mt < 4; mt++) {
        const int mrow = m0 + warp_m * 64 + mt * 16 + grp;
#pragma unroll
        for (int nt = 0; nt < 4; nt++) {
            const int col = n0 + warp_n * 32 + nt * 8 + 2 * qid;
            float b0 = bias ? bias[col] : 0.f;
            float b1 = bias ? bias[col + 1] : 0.f;
            float2 v0 = make_float2(acc[mt][nt][0] + b0, acc[mt][nt][1] + b1);
            float2 v1 = make_float2(acc[mt][nt][2] + b0, acc[mt][nt][3] + b1);
            *(float2*)(C + (size_t)mrow * N + col) = v0;
            *(float2*)(C + (size_t)(mrow + 8) * N + col) = v1;
        }
    }
}

// ---------------- RoPE on q and k sections of qkv ----------------
__global__ void rope_kernel(float* __restrict__ qkv, const int* __restrict__ positions)
{
    int idx = blockIdx.x * blockDim.x + threadIdx.x;   // MROWS * NHEAD * 64
    if (idx >= MROWS * NHEAD * 64) return;
    const int i = idx & 63;            // pair index 0..63
    const int h = (idx >> 6) & 31;     // head
    const int m = idx >> 11;           // row 0..4095

    const float pos = (float)positions[m];
    const float inv_freq = powf(10000.0f, -(float)i / 64.0f);
    const float ang = pos * inv_freq;
    const float c = cosf(ang);
    const float s = sinf(ang);

    float* qp = qkv + (size_t)m * QKV_N + h * HDIM + i;
    float x1 = qp[0], x2 = qp[64];
    qp[0]  = x1 * c - x2 * s;
    qp[64] = x2 * c + x1 * s;
    float* kp = qp + HID;
    x1 = kp[0]; x2 = kp[64];
    kp[0]  = x1 * c - x2 * s;
    kp[64] = x2 * c + x1 * s;
}

// ---------------- flash attention (fp32, causal) ----------------
#define QTS 64
#define KTS 64
#define TSTRIDE 132
#define PSTRIDE 65
#define FLASH_SMEM_FLOATS (QTS*TSTRIDE + KTS*TSTRIDE + QTS*PSTRIDE + 3*QTS)
#define FLASH_SMEM_BYTES (FLASH_SMEM_FLOATS * 4)

__global__ __launch_bounds__(256, 2)
void flash_kernel(const float* __restrict__ qkv, float* __restrict__ ctx)
{
    const int qt = blockIdx.x;
    const int h  = blockIdx.y;
    const int b  = blockIdx.z;

    extern __shared__ float smf[];
    float* Qs   = smf;
    float* KVs  = Qs + QTS * TSTRIDE;
    float* sP   = KVs + KTS * TSTRIDE;
    float* mrow = sP + QTS * PSTRIDE;
    float* lrow = mrow + QTS;
    float* arow = lrow + QTS;

    const int tid = threadIdx.x;
    const int ty = tid >> 4;
    const int tx = tid & 15;
    const float scale = 0.08838834764831845f;

    const float* qbase = qkv + (size_t)(b * SLEN + qt * QTS) * QKV_N + h * HDIM;
    for (int i = tid; i < QTS * HDIM / 4; i += 256) {
        const int row = i >> 5;
        const int c4  = i & 31;
        float4 v = *(const float4*)(qbase + (size_t)row * QKV_N + c4 * 4);
        float* dst = Qs + row * TSTRIDE + c4 * 4;
        dst[0] = v.x; dst[1] = v.y; dst[2] = v.z; dst[3] = v.w;
    }
    if (tid < QTS) { mrow[tid] = -INFINITY; lrow[tid] = 0.f; }

    float acc[4][8];
#pragma unroll
    for (int i = 0; i < 4; i++)
#pragma unroll
        for (int j = 0; j < 8; j++) acc[i][j] = 0.f;

    for (int kt = 0; kt <= qt; kt++) {
        const float* kbase = qkv + (size_t)(b * SLEN + kt * KTS) * QKV_N + HID + h * HDIM;
        __syncthreads();
        for (int i = tid; i < KTS * HDIM / 4; i += 256) {
            const int row = i >> 5;
            const int c4  = i & 31;
            float4 v = *(const float4*)(kbase + (size_t)row * QKV_N + c4 * 4);
            float* dst = KVs + row * TSTRIDE + c4 * 4;
            dst[0] = v.x; dst[1] = v.y; dst[2] = v.z; dst[3] = v.w;
        }
        __syncthreads();

        float sc[4][4];
#pragma unroll
        for (int i = 0; i < 4; i++)
#pragma unroll
            for (int j = 0; j < 4; j++) sc[i][j] = 0.f;

#pragma unroll 4
        for (int d = 0; d < HDIM; d++) {
            float qa[4], kb[4];
#pragma unroll
            for (int i = 0; i < 4; i++) qa[i] = Qs[(ty * 4 + i) * TSTRIDE + d];
#pragma unroll
            for (int j = 0; j < 4; j++) kb[j] = KVs[(tx * 4 + j) * TSTRIDE + d];
#pragma unroll
            for (int i = 0; i < 4; i++)
#pragma unroll
                for (int j = 0; j < 4; j++) sc[i][j] = fmaf(qa[i], kb[j], sc[i][j]);
        }

        const int qrow0 = qt * QTS + ty * 4;
        const int kcol0 = kt * KTS + tx * 4;
#pragma unroll
        for (int i = 0; i < 4; i++)
#pragma unroll
            for (int j = 0; j < 4; j++) {
                float s = sc[i][j] * scale;
                if (kt == qt && (kcol0 + j) > (qrow0 + i)) s = -INFINITY;
                sP[(ty * 4 + i) * PSTRIDE + tx * 4 + j] = s;
            }
        __syncthreads();

        const float* vbase = kbase + HID;
        for (int i = tid; i < KTS * HDIM / 4; i += 256) {
            const int row = i >> 5;
            const int c4  = i & 31;
            float4 v = *(const float4*)(vbase + (size_t)row * QKV_N + c4 * 4);
            float* dst = KVs + row * TSTRIDE + c4 * 4;
            dst[0] = v.x; dst[1] = v.y; dst[2] = v.z; dst[3] = v.w;
        }

        if (tid < QTS) {
            const int r = tid;
            float m_old = mrow[r];
            float m_new = m_old;
            for (int c = 0; c < KTS; c++) m_new = fmaxf(m_new, sP[r * PSTRIDE + c]);
            const float al = expf(m_old - m_new);
            float lsum = 0.f;
            for (int c = 0; c < KTS; c++) {
                float p = expf(sP[r * PSTRIDE + c] - m_new);
                sP[r * PSTRIDE + c] = p;
                lsum += p;
            }
            mrow[r] = m_new;
            lrow[r] = lrow[r] * al + lsum;
            arow[r] = al;
        }
        __syncthreads();

#pragma unroll
        for (int i = 0; i < 4; i++) {
            const float al = arow[ty * 4 + i];
#pragma unroll
            for (int j = 0; j < 8; j++) acc[i][j] *= al;
        }
#pragma unroll 4
        for (int c = 0; c < KTS; c++) {
            float p[4];
#pragma unroll
            for (int i = 0; i < 4; i++) p[i] = sP[(ty * 4 + i) * PSTRIDE + c];
            float4 v0 = *(const float4*)(KVs + c * TSTRIDE + tx * 8);
            float4 v1 = *(const float4*)(KVs + c * TSTRIDE + tx * 8 + 4);
#pragma unroll
            for (int i = 0; i < 4; i++) {
                acc[i][0] = fmaf(p[i], v0.x, acc[i][0]);
                acc[i][1] = fmaf(p[i], v0.y, acc[i][1]);
                acc[i][2] = fmaf(p[i], v0.z, acc[i][2]);
                acc[i][3] = fmaf(p[i], v0.w, acc[i][3]);
                acc[i][4] = fmaf(p[i], v1.x, acc[i][4]);
                acc[i][5] = fmaf(p[i], v1.y, acc[i][5]);
                acc[i][6] = fmaf(p[i], v1.z, acc[i][6]);
                acc[i][7] = fmaf(p[i], v1.w, acc[i][7]);
            }
        }
    }

    float* obase = ctx + (size_t)(b * SLEN + qt * QTS) * HID + h * HDIM;
#pragma unroll
    for (int i = 0; i < 4; i++) {
        const int r = ty * 4 + i;
        const float inv = 1.0f / lrow[r];
#pragma unroll
        for (int j = 0; j < 8; j++)
            obase[(size_t)r * HID + tx * 8 + j] = acc[i][j] * inv;
    }
}

// ---------------- launch ----------------
extern "C" void kernel_launch(void* const* d_in, const int* in_sizes, int n_in,
                              void* d_out, int out_size)
{
    const float* hs    = (const float*)d_in[0];
    const int*   pos   = (const int*)d_in[1];
    const float* Wqkv  = (const float*)d_in[2];
    const float* bqkv  = (const float*)d_in[3];
    const float* Wo    = (const float*)d_in[4];
    float* out = (float*)d_out;

    float *qkv, *ctx;
    cudaGetSymbolAddress((void**)&qkv, g_qkv);
    cudaGetSymbolAddress((void**)&ctx, g_ctx);

    static int configured = 0;
    if (!configured) {
        cudaFuncSetAttribute(gemm_tf32_kernel, cudaFuncAttributeMaxDynamicSharedMemorySize,
                             GEMM_SMEM_BYTES);
        cudaFuncSetAttribute(flash_kernel, cudaFuncAttributeMaxDynamicSharedMemorySize,
                             FLASH_SMEM_BYTES);
        configured = 1;
    }

    // 1) qkv = hs @ W_qkv + b   (3xTF32 tensor cores)
    {
        dim3 grid(QKV_N / BN, MROWS / BM);   // (96, 32)
        gemm_tf32_kernel<<<grid, 256, GEMM_SMEM_BYTES>>>(hs, Wqkv, bqkv, qkv,
                                                         MROWS, QKV_N, HID);
    }
    // 2) RoPE
    {
        int total = MROWS * NHEAD * 64;
        rope_kernel<<<(total + 255) / 256, 256>>>(qkv, pos);
    }
    // 3) causal flash attention -> ctx
    {
        dim3 grid(SLEN / QTS, NHEAD, BATCH);
        flash_kernel<<<grid, 256, FLASH_SMEM_BYTES>>>(qkv, ctx);
    }
    // 4) out = ctx @ W_o   (3xTF32 tensor cores)
    {
        dim3 grid(HID / BN, MROWS / BM);     // (32, 32)
        gemm_tf32_kernel<<<grid, 256, GEMM_SMEM_BYTES>>>(ctx, Wo, nullptr, out,
                                                         MROWS, HID, HID);
    }
}

// round 4
// speedup vs baseline: 2.0994x; 1.5349x over previous
#include <cuda_runtime.h>
#include <cuda_bf16.h>
#include <math.h>

// Problem constants
#define BATCH 2
#define SLEN 2048
#define HID 4096
#define NHEAD 32
#define HDIM 128
#define MROWS (BATCH * SLEN)       // 4096
#define QKV_N (3 * HID)            // 12288

// ---------------- scratch (no allocations allowed) ----------------
__device__ float g_qkv[(size_t)MROWS * QKV_N];   // 201 MB
__device__ float g_ctx[(size_t)MROWS * HID];     // 67 MB
// bf16 split operands
__device__ __nv_bfloat16 g_hs_hi[(size_t)MROWS * HID];
__device__ __nv_bfloat16 g_hs_lo[(size_t)MROWS * HID];
__device__ __nv_bfloat16 g_ctx_hi[(size_t)MROWS * HID];
__device__ __nv_bfloat16 g_ctx_lo[(size_t)MROWS * HID];
__device__ __nv_bfloat16 g_wqkv_hi[(size_t)QKV_N * HID];   // transposed [N][K]
__device__ __nv_bfloat16 g_wqkv_lo[(size_t)QKV_N * HID];
__device__ __nv_bfloat16 g_wo_hi[(size_t)HID * HID];       // transposed [N][K]
__device__ __nv_bfloat16 g_wo_lo[(size_t)HID * HID];

// ---------------- split helpers ----------------
__device__ __forceinline__ void split_bf16(float x, __nv_bfloat16& h, __nv_bfloat16& l)
{
    h = __float2bfloat16(x);
    l = __float2bfloat16(x - __bfloat162float(h));
}

// elementwise split (no transpose): src [n] f32 -> hi/lo bf16
__global__ void split_kernel(const float* __restrict__ src,
                             __nv_bfloat16* __restrict__ hi,
                             __nv_bfloat16* __restrict__ lo, int n4)
{
    int i = blockIdx.x * blockDim.x + threadIdx.x;
    if (i >= n4) return;
    float4 v = ((const float4*)src)[i];
    __nv_bfloat16 h0, h1, h2, h3, l0, l1, l2, l3;
    split_bf16(v.x, h0, l0); split_bf16(v.y, h1, l1);
    split_bf16(v.z, h2, l2); split_bf16(v.w, h3, l3);
    __nv_bfloat162* hp = (__nv_bfloat162*)(hi + (size_t)i * 4);
    __nv_bfloat162* lp = (__nv_bfloat162*)(lo + (size_t)i * 4);
    hp[0] = __nv_bfloat162(h0, h1); hp[1] = __nv_bfloat162(h2, h3);
    lp[0] = __nv_bfloat162(l0, l1); lp[1] = __nv_bfloat162(l2, l3);
}

// transpose + split: W [K][N] f32 -> Whi/Wlo [N][K] bf16
__global__ void transpose_split_kernel(const float* __restrict__ W,
                                       __nv_bfloat16* __restrict__ hi,
                                       __nv_bfloat16* __restrict__ lo,
                                       int K, int N)
{
    __shared__ float t[32][33];
    const int n0 = blockIdx.x * 32;
    const int k0 = blockIdx.y * 32;
    const int tx = threadIdx.x;          // 0..31
    const int ty = threadIdx.y;          // 0..7
#pragma unroll
    for (int j = 0; j < 32; j += 8)
        t[ty + j][tx] = W[(size_t)(k0 + ty + j) * N + n0 + tx];
    __syncthreads();
#pragma unroll
    for (int j = 0; j < 32; j += 8) {
        float x = t[tx][ty + j];
        __nv_bfloat16 h, l;
        split_bf16(x, h, l);
        size_t o = (size_t)(n0 + ty + j) * K + k0 + tx;
        hi[o] = h;
        lo[o] = l;
    }
}

// ================= bf16-split tensor-core GEMM =================
// C[MxN] = A[MxK] * Bt[NxK]^T (+bias); A,Bt given as hi/lo bf16 arrays.
// acc = Ahi*Bhi + Ahi*Blo + Alo*Bhi  (m16n8k16 bf16 MMA, fp32 accum)
#define BM 128
#define BN 128
#define BK 32
#define SSTRIDE 40                       // bf16 elems per smem row (80B, conflict-free)
#define TILE_ELEMS (128 * SSTRIDE)       // 5120
#define STAGE_ELEMS (4 * TILE_ELEMS)     // Ahi, Alo, Bhi, Blo
#define GEMM_SMEM_BYTES (2 * STAGE_ELEMS * 2)   // 81920

#define CP_ASYNC16(dst, src) \
    asm volatile("cp.async.cg.shared.global [%0], [%1], 16;\n" :: "r"(dst), "l"(src))
#define CP_COMMIT() asm volatile("cp.async.commit_group;\n" ::: "memory")
#define CP_WAIT(n)  asm volatile("cp.async.wait_group %0;\n" :: "n"(n) : "memory")

__device__ __forceinline__ void mma_bf16(float* c, const unsigned* a, const unsigned* b)
{
    asm volatile(
        "mma.sync.aligned.m16n8k16.row.col.f32.bf16.bf16.f32 "
        "{%0,%1,%2,%3},{%4,%5,%6,%7},{%8,%9},{%0,%1,%2,%3};"
        : "+f"(c[0]), "+f"(c[1]), "+f"(c[2]), "+f"(c[3])
        : "r"(a[0]), "r"(a[1]), "r"(a[2]), "r"(a[3]), "r"(b[0]), "r"(b[1]));
}

__global__ __launch_bounds__(256)
void gemm_bf16split_kernel(const __nv_bfloat16* __restrict__ Ahi,
                           const __nv_bfloat16* __restrict__ Alo,
                           const __nv_bfloat16* __restrict__ Bhi,
                           const __nv_bfloat16* __restrict__ Blo,
                           const float* __restrict__ bias, float* __restrict__ C,
                           int M, int N, int K)
{
    extern __shared__ __nv_bfloat16 sm[];
    const int tid = threadIdx.x;
    const int wid = tid >> 5;
    const int lane = tid & 31;
    const int grp = lane >> 2;     // 0..7
    const int qid = lane & 3;      // 0..3
    const int warp_m = wid >> 2;   // 0..1  (64 rows)
    const int warp_n = wid & 3;    // 0..3  (32 cols)

    const int m0 = blockIdx.y * BM;
    const int n0 = blockIdx.x * BN;

    float acc[4][4][4];
#pragma unroll
    for (int i = 0; i < 4; i++)
#pragma unroll
        for (int j = 0; j < 4; j++)
#pragma unroll
            for (int r = 0; r < 4; r++) acc[i][j][r] = 0.f;

    unsigned smem_base = (unsigned)__cvta_generic_to_shared(sm);

    const int NIT = K / BK;
    const int lrow = tid >> 2;     // 0..63? no: tid/4 -> 0..63 ... need 128 rows / 2 chunks
    // loader: each array has 128 rows x 4 chunks of 16B = 512 chunks; 2 per thread.

    auto load_stage = [&](int stage, int k0) {
        unsigned sbase = smem_base + (unsigned)(stage * STAGE_ELEMS) * 2u;
        const __nv_bfloat16* gsrc[4] = {Ahi, Alo, Bhi, Blo};
        const int gm0[4] = {m0, m0, n0, n0};
#pragma unroll
        for (int arr = 0; arr < 4; arr++) {
            unsigned sa = sbase + (unsigned)(arr * TILE_ELEMS) * 2u;
            const __nv_bfloat16* g = gsrc[arr];
#pragma unroll
            for (int p = 0; p < 2; p++) {
                int i = p * 256 + tid;
                int row = i >> 2;          // 0..127
                int c = i & 3;             // 16B chunk
                const __nv_bfloat16* src = g + (size_t)(gm0[arr] + row) * K + k0 + c * 8;
                CP_ASYNC16(sa + (unsigned)(row * SSTRIDE + c * 8) * 2u, src);
            }
        }
    };

    load_stage(0, 0);
    CP_COMMIT();

    int stage = 0;
    for (int it = 0; it < NIT; it++) {
        if (it + 1 < NIT) {
            load_stage(stage ^ 1, (it + 1) * BK);
            CP_COMMIT();
            CP_WAIT(1);
        } else {
            CP_WAIT(0);
        }
        __syncthreads();

        const __nv_bfloat16* As_hi = sm + stage * STAGE_ELEMS;
        const __nv_bfloat16* As_lo = As_hi + TILE_ELEMS;
        const __nv_bfloat16* Bs_hi = As_lo + TILE_ELEMS;
        const __nv_bfloat16* Bs_lo = Bs_hi + TILE_ELEMS;

#pragma unroll
        for (int kk = 0; kk < 2; kk++) {
            const int kof = kk * 16 + 2 * qid;
            unsigned ahi[4][4], bhi[4][2];
            // load hi fragments
#pragma unroll
            for (int mt = 0; mt < 4; mt++) {
                const int row = warp_m * 64 + mt * 16 + grp;
                const __nv_bfloat16* p = As_hi + row * SSTRIDE + kof;
                ahi[mt][0] = *(const unsigned*)(p);
                ahi[mt][1] = *(const unsigned*)(p + 8 * SSTRIDE);
                ahi[mt][2] = *(const unsigned*)(p + 8);
                ahi[mt][3] = *(const unsigned*)(p + 8 * SSTRIDE + 8);
            }
#pragma unroll
            for (int nt = 0; nt < 4; nt++) {
                const int n = warp_n * 32 + nt * 8 + grp;
                const __nv_bfloat16* p = Bs_hi + n * SSTRIDE + kof;
                bhi[nt][0] = *(const unsigned*)(p);
                bhi[nt][1] = *(const unsigned*)(p + 8);
            }
            // hi * hi
#pragma unroll
            for (int mt = 0; mt < 4; mt++)
#pragma unroll
                for (int nt = 0; nt < 4; nt++)
                    mma_bf16(acc[mt][nt], ahi[mt], bhi[nt]);
            // hi * lo
            {
                unsigned blo[4][2];
#pragma unroll
                for (int nt = 0; nt < 4; nt++) {
                    const int n = warp_n * 32 + nt * 8 + grp;
                    const __nv_bfloat16* p = Bs_lo + n * SSTRIDE + kof;
                    blo[nt][0] = *(const unsigned*)(p);
                    blo[nt][1] = *(const unsigned*)(p + 8);
                }
#pragma unroll
                for (int mt = 0; mt < 4; mt++)
#pragma unroll
                    for (int nt = 0; nt < 4; nt++)
                        mma_bf16(acc[mt][nt], ahi[mt], blo[nt]);
            }
            // lo * hi
            {
                unsigned alo[4][4];
#pragma unroll
                for (int mt = 0; mt < 4; mt++) {
                    const int row = warp_m * 64 + mt * 16 + grp;
                    const __nv_bfloat16* p = As_lo + row * SSTRIDE + kof;
                    alo[mt][0] = *(const unsigned*)(p);
                    alo[mt][1] = *(const unsigned*)(p + 8 * SSTRIDE);
                    alo[mt][2] = *(const unsigned*)(p + 8);
                    alo[mt][3] = *(const unsigned*)(p + 8 * SSTRIDE + 8);
                }
#pragma unroll
                for (int mt = 0; mt < 4; mt++)
#pragma unroll
                    for (int nt = 0; nt < 4; nt++)
                        mma_bf16(acc[mt][nt], alo[mt], bhi[nt]);
            }
        }
        __syncthreads();
        stage ^= 1;
    }

#pragma unroll
    for (int mt = 0; mt < 4; mt++) {
        const int mrow = m0 + warp_m * 64 + mt * 16 + grp;
#pragma unroll
        for (int nt = 0; nt < 4; nt++) {
            const int col = n0 + warp_n * 32 + nt * 8 + 2 * qid;
            float b0 = bias ? bias[col] : 0.f;
            float b1 = bias ? bias[col + 1] : 0.f;
            float2 v0 = make_float2(acc[mt][nt][0] + b0, acc[mt][nt][1] + b1);
            float2 v1 = make_float2(acc[mt][nt][2] + b0, acc[mt][nt][3] + b1);
            *(float2*)(C + (size_t)mrow * N + col) = v0;
            *(float2*)(C + (size_t)(mrow + 8) * N + col) = v1;
        }
    }
}

// ---------------- RoPE on q and k sections of qkv ----------------
__global__ void rope_kernel(float* __restrict__ qkv, const int* __restrict__ positions)
{
    int idx = blockIdx.x * blockDim.x + threadIdx.x;
    if (idx >= MROWS * NHEAD * 64) return;
    const int i = idx & 63;
    const int h = (idx >> 6) & 31;
    const int m = idx >> 11;

    const float pos = (float)positions[m];
    const float inv_freq = powf(10000.0f, -(float)i / 64.0f);
    const float ang = pos * inv_freq;
    const float c = cosf(ang);
    const float s = sinf(ang);

    float* qp = qkv + (size_t)m * QKV_N + h * HDIM + i;
    float x1 = qp[0], x2 = qp[64];
    qp[0]  = x1 * c - x2 * s;
    qp[64] = x2 * c + x1 * s;
    float* kp = qp + HID;
    x1 = kp[0]; x2 = kp[64];
    kp[0]  = x1 * c - x2 * s;
    kp[64] = x2 * c + x1 * s;
}

// ---------------- flash attention (fp32, causal) ----------------
#define QTS 64
#define KTS 64
#define TSTRIDE 132
#define PSTRIDE 65
#define FLASH_SMEM_FLOATS (QTS*TSTRIDE + KTS*TSTRIDE + QTS*PSTRIDE + 3*QTS)
#define FLASH_SMEM_BYTES (FLASH_SMEM_FLOATS * 4)

__global__ __launch_bounds__(256, 2)
void flash_kernel(const float* __restrict__ qkv, float* __restrict__ ctx)
{
    const int qt = blockIdx.x;
    const int h  = blockIdx.y;
    const int b  = blockIdx.z;

    extern __shared__ float smf[];
    float* Qs   = smf;
    float* KVs  = Qs + QTS * TSTRIDE;
    float* sP   = KVs + KTS * TSTRIDE;
    float* mrow = sP + QTS * PSTRIDE;
    float* lrow = mrow + QTS;
    float* arow = lrow + QTS;

    const int tid = threadIdx.x;
    const int ty = tid >> 4;
    const int tx = tid & 15;
    const float scale = 0.08838834764831845f;

    const float* qbase = qkv + (size_t)(b * SLEN + qt * QTS) * QKV_N + h * HDIM;
    for (int i = tid; i < QTS * HDIM / 4; i += 256) {
        const int row = i >> 5;
        const int c4  = i & 31;
        float4 v = *(const float4*)(qbase + (size_t)row * QKV_N + c4 * 4);
        float* dst = Qs + row * TSTRIDE + c4 * 4;
        dst[0] = v.x; dst[1] = v.y; dst[2] = v.z; dst[3] = v.w;
    }
    if (tid < QTS) { mrow[tid] = -INFINITY; lrow[tid] = 0.f; }

    float acc[4][8];
#pragma unroll
    for (int i = 0; i < 4; i++)
#pragma unroll
        for (int j = 0; j < 8; j++) acc[i][j] = 0.f;

    for (int kt = 0; kt <= qt; kt++) {
        const float* kbase = qkv + (size_t)(b * SLEN + kt * KTS) * QKV_N + HID + h * HDIM;
        __syncthreads();
        for (int i = tid; i < KTS * HDIM / 4; i += 256) {
            const int row = i >> 5;
            const int c4  = i & 31;
            float4 v = *(const float4*)(kbase + (size_t)row * QKV_N + c4 * 4);
            float* dst = KVs + row * TSTRIDE + c4 * 4;
            dst[0] = v.x; dst[1] = v.y; dst[2] = v.z; dst[3] = v.w;
        }
        __syncthreads();

        float sc[4][4];
#pragma unroll
        for (int i = 0; i < 4; i++)
#pragma unroll
            for (int j = 0; j < 4; j++) sc[i][j] = 0.f;

#pragma unroll 4
        for (int d = 0; d < HDIM; d++) {
            float qa[4], kb[4];
#pragma unroll
            for (int i = 0; i < 4; i++) qa[i] = Qs[(ty * 4 + i) * TSTRIDE + d];
#pragma unroll
            for (int j = 0; j < 4; j++) kb[j] = KVs[(tx * 4 + j) * TSTRIDE + d];
#pragma unroll
            for (int i = 0; i < 4; i++)
#pragma unroll
                for (int j = 0; j < 4; j++) sc[i][j] = fmaf(qa[i], kb[j], sc[i][j]);
        }

        const int qrow0 = qt * QTS + ty * 4;
        const int kcol0 = kt * KTS + tx * 4;
#pragma unroll
        for (int i = 0; i < 4; i++)
#pragma unroll
            for (int j = 0; j < 4; j++) {
                float s = sc[i][j] * scale;
                if (kt == qt && (kcol0 + j) > (qrow0 + i)) s = -INFINITY;
                sP[(ty * 4 + i) * PSTRIDE + tx * 4 + j] = s;
            }
        __syncthreads();

        const float* vbase = kbase + HID;
        for (int i = tid; i < KTS * HDIM / 4; i += 256) {
            const int row = i >> 5;
            const int c4  = i & 31;
            float4 v = *(const float4*)(vbase + (size_t)row * QKV_N + c4 * 4);
            float* dst = KVs + row * TSTRIDE + c4 * 4;
            dst[0] = v.x; dst[1] = v.y; dst[2] = v.z; dst[3] = v.w;
        }

        if (tid < QTS) {
            const int r = tid;
            float m_old = mrow[r];
            float m_new = m_old;
            for (int c = 0; c < KTS; c++) m_new = fmaxf(m_new, sP[r * PSTRIDE + c]);
            const float al = expf(m_old - m_new);
            float lsum = 0.f;
            for (int c = 0; c < KTS; c++) {
                float p = expf(sP[r * PSTRIDE + c] - m_new);
                sP[r * PSTRIDE + c] = p;
                lsum += p;
            }
            mrow[r] = m_new;
            lrow[r] = lrow[r] * al + lsum;
            arow[r] = al;
        }
        __syncthreads();

#pragma unroll
        for (int i = 0; i < 4; i++) {
            const float al = arow[ty * 4 + i];
#pragma unroll
            for (int j = 0; j < 8; j++) acc[i][j] *= al;
        }
#pragma unroll 4
        for (int c = 0; c < KTS; c++) {
            float p[4];
#pragma unroll
            for (int i = 0; i < 4; i++) p[i] = sP[(ty * 4 + i) * PSTRIDE + c];
            float4 v0 = *(const float4*)(KVs + c * TSTRIDE + tx * 8);
            float4 v1 = *(const float4*)(KVs + c * TSTRIDE + tx * 8 + 4);
#pragma unroll
            for (int i = 0; i < 4; i++) {
                acc[i][0] = fmaf(p[i], v0.x, acc[i][0]);
                acc[i][1] = fmaf(p[i], v0.y, acc[i][1]);
                acc[i][2] = fmaf(p[i], v0.z, acc[i][2]);
                acc[i][3] = fmaf(p[i], v0.w, acc[i][3]);
                acc[i][4] = fmaf(p[i], v1.x, acc[i][4]);
                acc[i][5] = fmaf(p[i], v1.y, acc[i][5]);
                acc[i][6] = fmaf(p[i], v1.z, acc[i][6]);
                acc[i][7] = fmaf(p[i], v1.w, acc[i][7]);
            }
        }
    }

    float* obase = ctx + (size_t)(b * SLEN + qt * QTS) * HID + h * HDIM;
#pragma unroll
    for (int i = 0; i < 4; i++) {
        const int r = ty * 4 + i;
        const float inv = 1.0f / lrow[r];
#pragma unroll
        for (int j = 0; j < 8; j++)
            obase[(size_t)r * HID + tx * 8 + j] = acc[i][j] * inv;
    }
}

// ---------------- launch ----------------
extern "C" void kernel_launch(void* const* d_in, const int* in_sizes, int n_in,
                              void* d_out, int out_size)
{
    const float* hs    = (const float*)d_in[0];
    const int*   pos   = (const int*)d_in[1];
    const float* Wqkv  = (const float*)d_in[2];
    const float* bqkv  = (const float*)d_in[3];
    const float* Wo    = (const float*)d_in[4];
    float* out = (float*)d_out;

    float *qkv, *ctx;
    __nv_bfloat16 *hs_hi, *hs_lo, *ctx_hi, *ctx_lo, *wqkv_hi, *wqkv_lo, *wo_hi, *wo_lo;
    cudaGetSymbolAddress((void**)&qkv, g_qkv);
    cudaGetSymbolAddress((void**)&ctx, g_ctx);
    cudaGetSymbolAddress((void**)&hs_hi, g_hs_hi);
    cudaGetSymbolAddress((void**)&hs_lo, g_hs_lo);
    cudaGetSymbolAddress((void**)&ctx_hi, g_ctx_hi);
    cudaGetSymbolAddress((void**)&ctx_lo, g_ctx_lo);
    cudaGetSymbolAddress((void**)&wqkv_hi, g_wqkv_hi);
    cudaGetSymbolAddress((void**)&wqkv_lo, g_wqkv_lo);
    cudaGetSymbolAddress((void**)&wo_hi, g_wo_hi);
    cudaGetSymbolAddress((void**)&wo_lo, g_wo_lo);

    static int configured = 0;
    if (!configured) {
        cudaFuncSetAttribute(gemm_bf16split_kernel,
                             cudaFuncAttributeMaxDynamicSharedMemorySize, GEMM_SMEM_BYTES);
        cudaFuncSetAttribute(flash_kernel,
                             cudaFuncAttributeMaxDynamicSharedMemorySize, FLASH_SMEM_BYTES);
        configured = 1;
    }

    // 0a) split hidden_states
    {
        int n4 = MROWS * HID / 4;
        split_kernel<<<(n4 + 255) / 256, 256>>>(hs, hs_hi, hs_lo, n4);
    }
    // 0b) transpose + split W_qkv -> [QKV_N][HID]
    {
        dim3 grid(QKV_N / 32, HID / 32);
        transpose_split_kernel<<<grid, dim3(32, 8)>>>(Wqkv, wqkv_hi, wqkv_lo, HID, QKV_N);
    }
    // 1) qkv = hs @ W_qkv + b
    {
        dim3 grid(QKV_N / BN, MROWS / BM);   // (96, 32)
        gemm_bf16split_kernel<<<grid, 256, GEMM_SMEM_BYTES>>>(
            hs_hi, hs_lo, wqkv_hi, wqkv_lo, bqkv, qkv, MROWS, QKV_N, HID);
    }
    // 2) RoPE
    {
        int total = MROWS * NHEAD * 64;
        rope_kernel<<<(total + 255) / 256, 256>>>(qkv, pos);
    }
    // 3) causal flash attention -> ctx
    {
        dim3 grid(SLEN / QTS, NHEAD, BATCH);
        flash_kernel<<<grid, 256, FLASH_SMEM_BYTES>>>(qkv, ctx);
    }
    // 0c) split ctx ; transpose + split W_o
    {
        int n4 = MROWS * HID / 4;
        split_kernel<<<(n4 + 255) / 256, 256>>>(ctx, ctx_hi, ctx_lo, n4);
        dim3 grid(HID / 32, HID / 32);
        transpose_split_kernel<<<grid, dim3(32, 8)>>>(Wo, wo_hi, wo_lo, HID, HID);
    }
    // 4) out = ctx @ W_o
    {
        dim3 grid(HID / BN, MROWS / BM);     // (32, 32)
        gemm_bf16split_kernel<<<grid, 256, GEMM_SMEM_BYTES>>>(
            ctx_hi, ctx_lo, wo_hi, wo_lo, nullptr, out, MROWS, HID, HID);
    }
}

// round 5
// speedup vs baseline: 3.1571x; 1.5038x over previous
#include <cuda_runtime.h>
#include <cuda_bf16.h>
#include <math.h>

// Problem constants
#define BATCH 2
#define SLEN 2048
#define HID 4096
#define NHEAD 32
#define HDIM 128
#define MROWS (BATCH * SLEN)       // 4096
#define QKV_N (3 * HID)            // 12288

// ---------------- scratch (no allocations allowed) ----------------
__device__ float g_qkv[(size_t)MROWS * QKV_N];   // 201 MB
__device__ float g_ctx[(size_t)MROWS * HID];     // 67 MB
// bf16 split operands for GEMMs
__device__ __nv_bfloat16 g_hs_hi[(size_t)MROWS * HID];
__device__ __nv_bfloat16 g_hs_lo[(size_t)MROWS * HID];
__device__ __nv_bfloat16 g_ctx_hi[(size_t)MROWS * HID];
__device__ __nv_bfloat16 g_ctx_lo[(size_t)MROWS * HID];
__device__ __nv_bfloat16 g_wqkv_hi[(size_t)QKV_N * HID];   // transposed [N][K]
__device__ __nv_bfloat16 g_wqkv_lo[(size_t)QKV_N * HID];
__device__ __nv_bfloat16 g_wo_hi[(size_t)HID * HID];       // transposed [N][K]
__device__ __nv_bfloat16 g_wo_lo[(size_t)HID * HID];
// bf16 split q/k/v in [b][h][s][d] layout (after RoPE)
__device__ __nv_bfloat16 g_q_hi[(size_t)MROWS * HID];
__device__ __nv_bfloat16 g_q_lo[(size_t)MROWS * HID];
__device__ __nv_bfloat16 g_k_hi[(size_t)MROWS * HID];
__device__ __nv_bfloat16 g_k_lo[(size_t)MROWS * HID];
__device__ __nv_bfloat16 g_v_hi[(size_t)MROWS * HID];
__device__ __nv_bfloat16 g_v_lo[(size_t)MROWS * HID];

// ---------------- helpers ----------------
__device__ __forceinline__ void split_bf16(float x, __nv_bfloat16& h, __nv_bfloat16& l)
{
    h = __float2bfloat16(x);
    l = __float2bfloat16(x - __bfloat162float(h));
}

// pack two floats to bf16x2 (x -> low half, y -> high half)
__device__ __forceinline__ unsigned pack_bf16x2(float x, float y)
{
    unsigned r;
    asm("cvt.rn.bf16x2.f32 %0, %1, %2;" : "=r"(r) : "f"(y), "f"(x));
    return r;
}

#define CP_ASYNC16(dst, src) \
    asm volatile("cp.async.cg.shared.global [%0], [%1], 16;\n" :: "r"(dst), "l"(src))
#define CP_COMMIT() asm volatile("cp.async.commit_group;\n" ::: "memory")
#define CP_WAIT(n)  asm volatile("cp.async.wait_group %0;\n" :: "n"(n) : "memory")

__device__ __forceinline__ void mma_bf16(float* c, const unsigned* a, const unsigned* b)
{
    asm volatile(
        "mma.sync.aligned.m16n8k16.row.col.f32.bf16.bf16.f32 "
        "{%0,%1,%2,%3},{%4,%5,%6,%7},{%8,%9},{%0,%1,%2,%3};"
        : "+f"(c[0]), "+f"(c[1]), "+f"(c[2]), "+f"(c[3])
        : "r"(a[0]), "r"(a[1]), "r"(a[2]), "r"(a[3]), "r"(b[0]), "r"(b[1]));
}

// elementwise split: src [n] f32 -> hi/lo bf16
__global__ void split_kernel(const float* __restrict__ src,
                             __nv_bfloat16* __restrict__ hi,
                             __nv_bfloat16* __restrict__ lo, int n4)
{
    int i = blockIdx.x * blockDim.x + threadIdx.x;
    if (i >= n4) return;
    float4 v = ((const float4*)src)[i];
    __nv_bfloat16 h0, h1, h2, h3, l0, l1, l2, l3;
    split_bf16(v.x, h0, l0); split_bf16(v.y, h1, l1);
    split_bf16(v.z, h2, l2); split_bf16(v.w, h3, l3);
    __nv_bfloat162* hp = (__nv_bfloat162*)(hi + (size_t)i * 4);
    __nv_bfloat162* lp = (__nv_bfloat162*)(lo + (size_t)i * 4);
    hp[0] = __nv_bfloat162(h0, h1); hp[1] = __nv_bfloat162(h2, h3);
    lp[0] = __nv_bfloat162(l0, l1); lp[1] = __nv_bfloat162(l2, l3);
}

// transpose + split: W [K][N] f32 -> Whi/Wlo [N][K] bf16
__global__ void transpose_split_kernel(const float* __restrict__ W,
                                       __nv_bfloat16* __restrict__ hi,
                                       __nv_bfloat16* __restrict__ lo,
                                       int K, int N)
{
    __shared__ float t[32][33];
    const int n0 = blockIdx.x * 32;
    const int k0 = blockIdx.y * 32;
    const int tx = threadIdx.x;
    const int ty = threadIdx.y;
#pragma unroll
    for (int j = 0; j < 32; j += 8)
        t[ty + j][tx] = W[(size_t)(k0 + ty + j) * N + n0 + tx];
    __syncthreads();
#pragma unroll
    for (int j = 0; j < 32; j += 8) {
        float x = t[tx][ty + j];
        __nv_bfloat16 h, l;
        split_bf16(x, h, l);
        size_t o = (size_t)(n0 + ty + j) * K + k0 + tx;
        hi[o] = h;
        lo[o] = l;
    }
}

// ================= bf16-split tensor-core GEMM =================
#define BM 128
#define BN 128
#define BK 32
#define SSTRIDE 40
#define TILE_ELEMS (128 * SSTRIDE)
#define STAGE_ELEMS (4 * TILE_ELEMS)
#define GEMM_SMEM_BYTES (2 * STAGE_ELEMS * 2)   // 81920

__global__ __launch_bounds__(256)
void gemm_bf16split_kernel(const __nv_bfloat16* __restrict__ Ahi,
                           const __nv_bfloat16* __restrict__ Alo,
                           const __nv_bfloat16* __restrict__ Bhi,
                           const __nv_bfloat16* __restrict__ Blo,
                           const float* __restrict__ bias, float* __restrict__ C,
                           int M, int N, int K)
{
    extern __shared__ __nv_bfloat16 sm[];
    const int tid = threadIdx.x;
    const int wid = tid >> 5;
    const int lane = tid & 31;
    const int grp = lane >> 2;
    const int qid = lane & 3;
    const int warp_m = wid >> 2;
    const int warp_n = wid & 3;

    const int m0 = blockIdx.y * BM;
    const int n0 = blockIdx.x * BN;

    float acc[4][4][4];
#pragma unroll
    for (int i = 0; i < 4; i++)
#pragma unroll
        for (int j = 0; j < 4; j++)
#pragma unroll
            for (int r = 0; r < 4; r++) acc[i][j][r] = 0.f;

    unsigned smem_base = (unsigned)__cvta_generic_to_shared(sm);
    const int NIT = K / BK;

    auto load_stage = [&](int stage, int k0) {
        unsigned sbase = smem_base + (unsigned)(stage * STAGE_ELEMS) * 2u;
        const __nv_bfloat16* gsrc[4] = {Ahi, Alo, Bhi, Blo};
        const int gm0[4] = {m0, m0, n0, n0};
#pragma unroll
        for (int arr = 0; arr < 4; arr++) {
            unsigned sa = sbase + (unsigned)(arr * TILE_ELEMS) * 2u;
            const __nv_bfloat16* g = gsrc[arr];
#pragma unroll
            for (int p = 0; p < 2; p++) {
                int i = p * 256 + tid;
                int row = i >> 2;
                int c = i & 3;
                const __nv_bfloat16* src = g + (size_t)(gm0[arr] + row) * K + k0 + c * 8;
                CP_ASYNC16(sa + (unsigned)(row * SSTRIDE + c * 8) * 2u, src);
            }
        }
    };

    load_stage(0, 0);
    CP_COMMIT();

    int stage = 0;
    for (int it = 0; it < NIT; it++) {
        if (it + 1 < NIT) {
            load_stage(stage ^ 1, (it + 1) * BK);
            CP_COMMIT();
            CP_WAIT(1);
        } else {
            CP_WAIT(0);
        }
        __syncthreads();

        const __nv_bfloat16* As_hi = sm + stage * STAGE_ELEMS;
        const __nv_bfloat16* As_lo = As_hi + TILE_ELEMS;
        const __nv_bfloat16* Bs_hi = As_lo + TILE_ELEMS;
        const __nv_bfloat16* Bs_lo = Bs_hi + TILE_ELEMS;

#pragma unroll
        for (int kk = 0; kk < 2; kk++) {
            const int kof = kk * 16 + 2 * qid;
            unsigned ahi[4][4], bhi[4][2];
#pragma unroll
            for (int mt = 0; mt < 4; mt++) {
                const int row = warp_m * 64 + mt * 16 + grp;
                const __nv_bfloat16* p = As_hi + row * SSTRIDE + kof;
                ahi[mt][0] = *(const unsigned*)(p);
                ahi[mt][1] = *(const unsigned*)(p + 8 * SSTRIDE);
                ahi[mt][2] = *(const unsigned*)(p + 8);
                ahi[mt][3] = *(const unsigned*)(p + 8 * SSTRIDE + 8);
            }
#pragma unroll
            for (int nt = 0; nt < 4; nt++) {
                const int n = warp_n * 32 + nt * 8 + grp;
                const __nv_bfloat16* p = Bs_hi + n * SSTRIDE + kof;
                bhi[nt][0] = *(const unsigned*)(p);
                bhi[nt][1] = *(const unsigned*)(p + 8);
            }
#pragma unroll
            for (int mt = 0; mt < 4; mt++)
#pragma unroll
                for (int nt = 0; nt < 4; nt++)
                    mma_bf16(acc[mt][nt], ahi[mt], bhi[nt]);
            {
                unsigned blo[4][2];
#pragma unroll
                for (int nt = 0; nt < 4; nt++) {
                    const int n = warp_n * 32 + nt * 8 + grp;
                    const __nv_bfloat16* p = Bs_lo + n * SSTRIDE + kof;
                    blo[nt][0] = *(const unsigned*)(p);
                    blo[nt][1] = *(const unsigned*)(p + 8);
                }
#pragma unroll
                for (int mt = 0; mt < 4; mt++)
#pragma unroll
                    for (int nt = 0; nt < 4; nt++)
                        mma_bf16(acc[mt][nt], ahi[mt], blo[nt]);
            }
            {
                unsigned alo[4][4];
#pragma unroll
                for (int mt = 0; mt < 4; mt++) {
                    const int row = warp_m * 64 + mt * 16 + grp;
                    const __nv_bfloat16* p = As_lo + row * SSTRIDE + kof;
                    alo[mt][0] = *(const unsigned*)(p);
                    alo[mt][1] = *(const unsigned*)(p + 8 * SSTRIDE);
                    alo[mt][2] = *(const unsigned*)(p + 8);
                    alo[mt][3] = *(const unsigned*)(p + 8 * SSTRIDE + 8);
                }
#pragma unroll
                for (int mt = 0; mt < 4; mt++)
#pragma unroll
                    for (int nt = 0; nt < 4; nt++)
                        mma_bf16(acc[mt][nt], alo[mt], bhi[nt]);
            }
        }
        __syncthreads();
        stage ^= 1;
    }

#pragma unroll
    for (int mt = 0; mt < 4; mt++) {
        const int mrow = m0 + warp_m * 64 + mt * 16 + grp;
#pragma unroll
        for (int nt = 0; nt < 4; nt++) {
            const int col = n0 + warp_n * 32 + nt * 8 + 2 * qid;
            float b0 = bias ? bias[col] : 0.f;
            float b1 = bias ? bias[col + 1] : 0.f;
            float2 v0 = make_float2(acc[mt][nt][0] + b0, acc[mt][nt][1] + b1);
            float2 v1 = make_float2(acc[mt][nt][2] + b0, acc[mt][nt][3] + b1);
            *(float2*)(C + (size_t)mrow * N + col) = v0;
            *(float2*)(C + (size_t)(mrow + 8) * N + col) = v1;
        }
    }
}

// ---------------- fused RoPE + split + relayout ----------------
// reads fp32 qkv rows; writes q/k/v hi+lo bf16 in [b][h][s][d] layout.
__global__ void rope_split_kernel(const float* __restrict__ qkv,
                                  const int* __restrict__ positions)
{
    int idx = blockIdx.x * blockDim.x + threadIdx.x;
    if (idx >= MROWS * NHEAD * 64) return;
    const int i = idx & 63;            // pair index
    const int h = (idx >> 6) & 31;
    const int m = idx >> 11;           // global row
    const int b = m >> 11;
    const int s = m & 2047;

    const float pos = (float)positions[m];
    const float inv_freq = powf(10000.0f, -(float)i / 64.0f);
    const float ang = pos * inv_freq;
    const float c = cosf(ang);
    const float sn = sinf(ang);

    const float* row = qkv + (size_t)m * QKV_N + h * HDIM;
    const size_t hb = ((size_t)((b * NHEAD + h) * SLEN) + s) * HDIM;

    // q
    {
        float x1 = row[i], x2 = row[i + 64];
        float y1 = x1 * c - x2 * sn;
        float y2 = x2 * c + x1 * sn;
        __nv_bfloat16 h1, l1, h2, l2;
        split_bf16(y1, h1, l1); split_bf16(y2, h2, l2);
        g_q_hi[hb + i] = h1; g_q_hi[hb + i + 64] = h2;
        g_q_lo[hb + i] = l1; g_q_lo[hb + i + 64] = l2;
    }
    // k
    {
        float x1 = row[HID + i], x2 = row[HID + i + 64];
        float y1 = x1 * c - x2 * sn;
        float y2 = x2 * c + x1 * sn;
        __nv_bfloat16 h1, l1, h2, l2;
        split_bf16(y1, h1, l1); split_bf16(y2, h2, l2);
        g_k_hi[hb + i] = h1; g_k_hi[hb + i + 64] = h2;
        g_k_lo[hb + i] = l1; g_k_lo[hb + i + 64] = l2;
    }
    // v (no rope)
    {
        float x1 = row[2 * HID + i], x2 = row[2 * HID + i + 64];
        __nv_bfloat16 h1, l1, h2, l2;
        split_bf16(x1, h1, l1); split_bf16(x2, h2, l2);
        g_v_hi[hb + i] = h1; g_v_hi[hb + i + 64] = h2;
        g_v_lo[hb + i] = l1; g_v_lo[hb + i + 64] = l2;
    }
}

// ---------------- tensor-core flash attention (bf16-split, causal) ----------------
#define AQT 128
#define AKT 64
#define QST 136
#define KST 136
#define VST 72
#define SM_QHI 0
#define SM_QLO (SM_QHI + AQT * QST)
#define SM_KHI (SM_QLO + AQT * QST)
#define SM_KLO (SM_KHI + AKT * KST)
#define SM_VHI (SM_KLO + AKT * KST)
#define SM_VLO (SM_VHI + AQT * VST)
#define ATT_SMEM_ELEMS (SM_VLO + AQT * VST)
#define ATT_SMEM_BYTES (ATT_SMEM_ELEMS * 2)   // 141312

__global__ __launch_bounds__(256)
void flash_mma_kernel(const __nv_bfloat16* __restrict__ qh, const __nv_bfloat16* __restrict__ ql,
                      const __nv_bfloat16* __restrict__ kh, const __nv_bfloat16* __restrict__ kl,
                      const __nv_bfloat16* __restrict__ vh, const __nv_bfloat16* __restrict__ vl,
                      float* __restrict__ ctx)
{
    extern __shared__ __nv_bfloat16 sma[];
    const int qt = blockIdx.x;
    const int h  = blockIdx.y;
    const int b  = blockIdx.z;
    const int tid = threadIdx.x;
    const int wid = tid >> 5;
    const int lane = tid & 31;
    const int grp = lane >> 2;
    const int qid = lane & 3;
    const size_t hb = ((size_t)(b * NHEAD + h)) * SLEN * HDIM;
    unsigned sbase = (unsigned)__cvta_generic_to_shared(sma);
    const float scale = 0.08838834764831845f;

    // load Q tile (128 x 128) hi+lo via cp.async
    {
        const __nv_bfloat16* g = qh + hb + (size_t)qt * AQT * HDIM;
#pragma unroll
        for (int p = 0; p < 8; p++) {
            int i = p * 256 + tid;
            int row = i >> 4, c = i & 15;
            CP_ASYNC16(sbase + (unsigned)(SM_QHI + row * QST + c * 8) * 2u, g + row * HDIM + c * 8);
        }
        g = ql + hb + (size_t)qt * AQT * HDIM;
#pragma unroll
        for (int p = 0; p < 8; p++) {
            int i = p * 256 + tid;
            int row = i >> 4, c = i & 15;
            CP_ASYNC16(sbase + (unsigned)(SM_QLO + row * QST + c * 8) * 2u, g + row * HDIM + c * 8);
        }
        CP_COMMIT();
    }

    float m0 = -1e30f, m1 = -1e30f, l0 = 0.f, l1 = 0.f;
    float o[16][4];
#pragma unroll
    for (int nt = 0; nt < 16; nt++)
#pragma unroll
        for (int r = 0; r < 4; r++) o[nt][r] = 0.f;

    const int qrow_warp = qt * AQT + wid * 16;
    const int nkt = 2 * qt + 2;

    for (int kt = 0; kt < nkt; kt++) {
        __syncthreads();   // previous iter done with K/V smem
        // K hi/lo via cp.async
        {
            const __nv_bfloat16* g = kh + hb + (size_t)kt * AKT * HDIM;
#pragma unroll
            for (int p = 0; p < 4; p++) {
                int i = p * 256 + tid;
                int row = i >> 4, c = i & 15;
                CP_ASYNC16(sbase + (unsigned)(SM_KHI + row * KST + c * 8) * 2u, g + row * HDIM + c * 8);
            }
            g = kl + hb + (size_t)kt * AKT * HDIM;
#pragma unroll
            for (int p = 0; p < 4; p++) {
                int i = p * 256 + tid;
                int row = i >> 4, c = i & 15;
                CP_ASYNC16(sbase + (unsigned)(SM_KLO + row * KST + c * 8) * 2u, g + row * HDIM + c * 8);
            }
            CP_COMMIT();
        }
        // V transposed into smem: Vt[d][kv]
        {
            const int kv = tid & 63;
            const int dg = tid >> 6;    // 0..3, 32 d's each
            uint4 tv[4];
            const __nv_bfloat16* g = vh + hb + (size_t)(kt * AKT + kv) * HDIM + dg * 32;
#pragma unroll
            for (int c = 0; c < 4; c++) tv[c] = *(const uint4*)(g + c * 8);
            const __nv_bfloat16* tb = (const __nv_bfloat16*)tv;
#pragma unroll
            for (int j = 0; j < 32; j++)
                sma[SM_VHI + (dg * 32 + j) * VST + kv] = tb[j];
            g = vl + hb + (size_t)(kt * AKT + kv) * HDIM + dg * 32;
#pragma unroll
            for (int c = 0; c < 4; c++) tv[c] = *(const uint4*)(g + c * 8);
#pragma unroll
            for (int j = 0; j < 32; j++)
                sma[SM_VLO + (dg * 32 + j) * VST + kv] = tb[j];
        }
        CP_WAIT(0);
        __syncthreads();

        const bool active = (kt * AKT <= qrow_warp + 15);
        if (active) {
            // ---- S = Q K^T (3-term bf16 split) ----
            float sreg[8][4];
#pragma unroll
            for (int nt = 0; nt < 8; nt++)
#pragma unroll
                for (int r = 0; r < 4; r++) sreg[nt][r] = 0.f;

#pragma unroll
            for (int d8 = 0; d8 < 8; d8++) {
                const int kof = d8 * 16 + 2 * qid;
                unsigned ahi[4], alo[4];
                {
                    const __nv_bfloat16* p = sma + SM_QHI + (wid * 16 + grp) * QST + kof;
                    ahi[0] = *(const unsigned*)(p);
                    ahi[1] = *(const unsigned*)(p + 8 * QST);
                    ahi[2] = *(const unsigned*)(p + 8);
                    ahi[3] = *(const unsigned*)(p + 8 * QST + 8);
                    const __nv_bfloat16* pl = sma + SM_QLO + (wid * 16 + grp) * QST + kof;
                    alo[0] = *(const unsigned*)(pl);
                    alo[1] = *(const unsigned*)(pl + 8 * QST);
                    alo[2] = *(const unsigned*)(pl + 8);
                    alo[3] = *(const unsigned*)(pl + 8 * QST + 8);
                }
#pragma unroll
                for (int nt = 0; nt < 8; nt++) {
                    unsigned bhi[2], blo[2];
                    const __nv_bfloat16* p = sma + SM_KHI + (nt * 8 + grp) * KST + kof;
                    bhi[0] = *(const unsigned*)(p);
                    bhi[1] = *(const unsigned*)(p + 8);
                    const __nv_bfloat16* pl = sma + SM_KLO + (nt * 8 + grp) * KST + kof;
                    blo[0] = *(const unsigned*)(pl);
                    blo[1] = *(const unsigned*)(pl + 8);
                    mma_bf16(sreg[nt], ahi, bhi);
                    mma_bf16(sreg[nt], ahi, blo);
                    mma_bf16(sreg[nt], alo, bhi);
                }
            }

            // ---- scale + causal mask ----
            const int row0 = qrow_warp + grp;
            const int row1 = row0 + 8;
            const bool need_mask = (kt * AKT + AKT - 1) > row0;  // conservative per-thread
#pragma unroll
            for (int nt = 0; nt < 8; nt++) {
                const int c0 = kt * AKT + nt * 8 + 2 * qid;
                const int c1 = c0 + 1;
                if (need_mask || (kt * AKT + AKT - 1) > row1) {
                    sreg[nt][0] = (c0 <= row0) ? sreg[nt][0] * scale : -1e30f;
                    sreg[nt][1] = (c1 <= row0) ? sreg[nt][1] * scale : -1e30f;
                    sreg[nt][2] = (c0 <= row1) ? sreg[nt][2] * scale : -1e30f;
                    sreg[nt][3] = (c1 <= row1) ? sreg[nt][3] * scale : -1e30f;
                } else {
                    sreg[nt][0] *= scale;
                    sreg[nt][1] *= scale;
                    sreg[nt][2] *= scale;
                    sreg[nt][3] *= scale;
                }
            }

            // ---- online softmax (register, quad-reduced) ----
            float tm0 = -1e30f, tm1 = -1e30f;
#pragma unroll
            for (int nt = 0; nt < 8; nt++) {
                tm0 = fmaxf(tm0, fmaxf(sreg[nt][0], sreg[nt][1]));
                tm1 = fmaxf(tm1, fmaxf(sreg[nt][2], sreg[nt][3]));
            }
            tm0 = fmaxf(tm0, __shfl_xor_sync(0xffffffffu, tm0, 1));
            tm0 = fmaxf(tm0, __shfl_xor_sync(0xffffffffu, tm0, 2));
            tm1 = fmaxf(tm1, __shfl_xor_sync(0xffffffffu, tm1, 1));
            tm1 = fmaxf(tm1, __shfl_xor_sync(0xffffffffu, tm1, 2));
            const float mn0 = fmaxf(m0, tm0);
            const float mn1 = fmaxf(m1, tm1);
            const float al0 = __expf(m0 - mn0);
            const float al1 = __expf(m1 - mn1);
            m0 = mn0; m1 = mn1;
            float ps0 = 0.f, ps1 = 0.f;
#pragma unroll
            for (int nt = 0; nt < 8; nt++) {
                sreg[nt][0] = __expf(sreg[nt][0] - m0);
                sreg[nt][1] = __expf(sreg[nt][1] - m0);
                sreg[nt][2] = __expf(sreg[nt][2] - m1);
                sreg[nt][3] = __expf(sreg[nt][3] - m1);
                ps0 += sreg[nt][0] + sreg[nt][1];
                ps1 += sreg[nt][2] + sreg[nt][3];
            }
            l0 = l0 * al0 + ps0;
            l1 = l1 * al1 + ps1;
#pragma unroll
            for (int nt = 0; nt < 16; nt++) {
                o[nt][0] *= al0; o[nt][1] *= al0;
                o[nt][2] *= al1; o[nt][3] *= al1;
            }

            // ---- O += P V (3-term bf16 split; P split in registers) ----
#pragma unroll
            for (int c = 0; c < 4; c++) {
                unsigned phi[4], plo[4];
#pragma unroll
                for (int half = 0; half < 2; half++) {
                    // half 0 -> regs (phi[0],phi[1]) from sreg[2c]; half 1 -> (phi[2],phi[3]) from sreg[2c+1]
                    const float x0 = sreg[2 * c + half][0];
                    const float x1 = sreg[2 * c + half][1];
                    const float x2 = sreg[2 * c + half][2];
                    const float x3 = sreg[2 * c + half][3];
                    __nv_bfloat16 h0 = __float2bfloat16(x0);
                    __nv_bfloat16 h1 = __float2bfloat16(x1);
                    __nv_bfloat16 h2 = __float2bfloat16(x2);
                    __nv_bfloat16 h3 = __float2bfloat16(x3);
                    phi[0 + 2 * half] = pack_bf16x2(__bfloat162float(h0), __bfloat162float(h1));
                    phi[1 + 2 * half] = pack_bf16x2(__bfloat162float(h2), __bfloat162float(h3));
                    plo[0 + 2 * half] = pack_bf16x2(x0 - __bfloat162float(h0), x1 - __bfloat162float(h1));
                    plo[1 + 2 * half] = pack_bf16x2(x2 - __bfloat162float(h2), x3 - __bfloat162float(h3));
                }
                // reorder: phi[0]=rows grp k-lo from sreg[2c][0,1]; phi[1]=rows grp+8 from sreg[2c][2,3];
                //          phi[2]=rows grp k-hi from sreg[2c+1][0,1]; phi[3]=rows grp+8 from sreg[2c+1][2,3]
                const int kof = 2 * qid + 16 * c;
#pragma unroll
                for (int nt = 0; nt < 16; nt++) {
                    unsigned bhi[2], blo[2];
                    const __nv_bfloat16* p = sma + SM_VHI + (nt * 8 + grp) * VST + kof;
                    bhi[0] = *(const unsigned*)(p);
                    bhi[1] = *(const unsigned*)(p + 8);
                    const __nv_bfloat16* pl = sma + SM_VLO + (nt * 8 + grp) * VST + kof;
                    blo[0] = *(const unsigned*)(pl);
                    blo[1] = *(const unsigned*)(pl + 8);
                    mma_bf16(o[nt], phi, bhi);
                    mma_bf16(o[nt], plo, bhi);
                    mma_bf16(o[nt], phi, blo);
                }
            }
        }
    }

    // final l reduction and write
    l0 += __shfl_xor_sync(0xffffffffu, l0, 1);
    l0 += __shfl_xor_sync(0xffffffffu, l0, 2);
    l1 += __shfl_xor_sync(0xffffffffu, l1, 1);
    l1 += __shfl_xor_sync(0xffffffffu, l1, 2);
    const float inv0 = 1.0f / l0;
    const float inv1 = 1.0f / l1;

    const int row0 = b * SLEN + qt * AQT + wid * 16 + grp;
#pragma unroll
    for (int nt = 0; nt < 16; nt++) {
        const int col = h * HDIM + nt * 8 + 2 * qid;
        *(float2*)(ctx + (size_t)row0 * HID + col) =
            make_float2(o[nt][0] * inv0, o[nt][1] * inv0);
        *(float2*)(ctx + (size_t)(row0 + 8) * HID + col) =
            make_float2(o[nt][2] * inv1, o[nt][3] * inv1);
    }
}

// ---------------- launch ----------------
extern "C" void kernel_launch(void* const* d_in, const int* in_sizes, int n_in,
                              void* d_out, int out_size)
{
    const float* hs    = (const float*)d_in[0];
    const int*   pos   = (const int*)d_in[1];
    const float* Wqkv  = (const float*)d_in[2];
    const float* bqkv  = (const float*)d_in[3];
    const float* Wo    = (const float*)d_in[4];
    float* out = (float*)d_out;

    float *qkv, *ctx;
    __nv_bfloat16 *hs_hi, *hs_lo, *ctx_hi, *ctx_lo, *wqkv_hi, *wqkv_lo, *wo_hi, *wo_lo;
    __nv_bfloat16 *q_hi, *q_lo, *k_hi, *k_lo, *v_hi, *v_lo;
    cudaGetSymbolAddress((void**)&qkv, g_qkv);
    cudaGetSymbolAddress((void**)&ctx, g_ctx);
    cudaGetSymbolAddress((void**)&hs_hi, g_hs_hi);
    cudaGetSymbolAddress((void**)&hs_lo, g_hs_lo);
    cudaGetSymbolAddress((void**)&ctx_hi, g_ctx_hi);
    cudaGetSymbolAddress((void**)&ctx_lo, g_ctx_lo);
    cudaGetSymbolAddress((void**)&wqkv_hi, g_wqkv_hi);
    cudaGetSymbolAddress((void**)&wqkv_lo, g_wqkv_lo);
    cudaGetSymbolAddress((void**)&wo_hi, g_wo_hi);
    cudaGetSymbolAddress((void**)&wo_lo, g_wo_lo);
    cudaGetSymbolAddress((void**)&q_hi, g_q_hi);
    cudaGetSymbolAddress((void**)&q_lo, g_q_lo);
    cudaGetSymbolAddress((void**)&k_hi, g_k_hi);
    cudaGetSymbolAddress((void**)&k_lo, g_k_lo);
    cudaGetSymbolAddress((void**)&v_hi, g_v_hi);
    cudaGetSymbolAddress((void**)&v_lo, g_v_lo);

    static int configured = 0;
    if (!configured) {
        cudaFuncSetAttribute(gemm_bf16split_kernel,
                             cudaFuncAttributeMaxDynamicSharedMemorySize, GEMM_SMEM_BYTES);
        cudaFuncSetAttribute(flash_mma_kernel,
                             cudaFuncAttributeMaxDynamicSharedMemorySize, ATT_SMEM_BYTES);
        configured = 1;
    }

    // 0a) split hidden_states ; 0b) transpose+split weights
    {
        int n4 = MROWS * HID / 4;
        split_kernel<<<(n4 + 255) / 256, 256>>>(hs, hs_hi, hs_lo, n4);
        dim3 g1(QKV_N / 32, HID / 32);
        transpose_split_kernel<<<g1, dim3(32, 8)>>>(Wqkv, wqkv_hi, wqkv_lo, HID, QKV_N);
        dim3 g2(HID / 32, HID / 32);
        transpose_split_kernel<<<g2, dim3(32, 8)>>>(Wo, wo_hi, wo_lo, HID, HID);
    }
    // 1) qkv = hs @ W_qkv + b
    {
        dim3 grid(QKV_N / BN, MROWS / BM);
        gemm_bf16split_kernel<<<grid, 256, GEMM_SMEM_BYTES>>>(
            hs_hi, hs_lo, wqkv_hi, wqkv_lo, bqkv, qkv, MROWS, QKV_N, HID);
    }
    // 2) RoPE + split + relayout
    {
        int total = MROWS * NHEAD * 64;
        rope_split_kernel<<<(total + 255) / 256, 256>>>(qkv, pos);
    }
    // 3) tensor-core causal flash attention -> ctx (fp32)
    {
        dim3 grid(SLEN / AQT, NHEAD, BATCH);   // (16, 32, 2)
        flash_mma_kernel<<<grid, 256, ATT_SMEM_BYTES>>>(q_hi, q_lo, k_hi, k_lo,
                                                        v_hi, v_lo, ctx);
    }
    // 3b) split ctx for O GEMM
    {
        int n4 = MROWS * HID / 4;
        split_kernel<<<(n4 + 255) / 256, 256>>>(ctx, ctx_hi, ctx_lo, n4);
    }
    // 4) out = ctx @ W_o
    {
        dim3 grid(HID / BN, MROWS / BM);
        gemm_bf16split_kernel<<<grid, 256, GEMM_SMEM_BYTES>>>(
            ctx_hi, ctx_lo, wo_hi, wo_lo, nullptr, out, MROWS, HID, HID);
    }
}

// round 7
// speedup vs baseline: 3.2784x; 1.0384x over previous
#include <cuda_runtime.h>
#include <cuda_bf16.h>
#include <math.h>

// Problem constants
#define BATCH 2
#define SLEN 2048
#define HID 4096
#define NHEAD 32
#define HDIM 128
#define MROWS (BATCH * SLEN)       // 4096
#define QKV_N (3 * HID)            // 12288

// ---------------- scratch (no allocations allowed) ----------------
__device__ float g_qkv[(size_t)MROWS * QKV_N];   // 201 MB
__device__ float g_ctx[(size_t)MROWS * HID];     // 67 MB
__device__ __nv_bfloat16 g_hs_hi[(size_t)MROWS * HID];
__device__ __nv_bfloat16 g_hs_lo[(size_t)MROWS * HID];
__device__ __nv_bfloat16 g_ctx_hi[(size_t)MROWS * HID];
__device__ __nv_bfloat16 g_ctx_lo[(size_t)MROWS * HID];
__device__ __nv_bfloat16 g_wqkv_hi[(size_t)QKV_N * HID];   // transposed [N][K]
__device__ __nv_bfloat16 g_wqkv_lo[(size_t)QKV_N * HID];
__device__ __nv_bfloat16 g_wo_hi[(size_t)HID * HID];       // transposed [N][K]
__device__ __nv_bfloat16 g_wo_lo[(size_t)HID * HID];
__device__ __nv_bfloat16 g_q_hi[(size_t)MROWS * HID];
__device__ __nv_bfloat16 g_q_lo[(size_t)MROWS * HID];
__device__ __nv_bfloat16 g_k_hi[(size_t)MROWS * HID];
__device__ __nv_bfloat16 g_k_lo[(size_t)MROWS * HID];
__device__ __nv_bfloat16 g_v_hi[(size_t)MROWS * HID];
__device__ __nv_bfloat16 g_v_lo[(size_t)MROWS * HID];

// ---------------- helpers ----------------
__device__ __forceinline__ void split_bf16(float x, __nv_bfloat16& h, __nv_bfloat16& l)
{
    h = __float2bfloat16(x);
    l = __float2bfloat16(x - __bfloat162float(h));
}

__device__ __forceinline__ unsigned pack_bf16x2(float x, float y)
{
    unsigned r;
    asm("cvt.rn.bf16x2.f32 %0, %1, %2;" : "=r"(r) : "f"(y), "f"(x));
    return r;
}

#define CP_ASYNC16(dst, src) \
    asm volatile("cp.async.cg.shared.global [%0], [%1], 16;\n" :: "r"(dst), "l"(src))
#define CP_COMMIT() asm volatile("cp.async.commit_group;\n" ::: "memory")
#define CP_WAIT(n)  asm volatile("cp.async.wait_group %0;\n" :: "n"(n) : "memory")

#define LDSM_X4(r0, r1, r2, r3, addr) \
    asm volatile("ldmatrix.sync.aligned.m8n8.x4.shared.b16 {%0,%1,%2,%3}, [%4];" \
        : "=r"(r0), "=r"(r1), "=r"(r2), "=r"(r3) : "r"(addr))

__device__ __forceinline__ void mma_bf16(float* c, const unsigned* a, const unsigned* b)
{
    asm volatile(
        "mma.sync.aligned.m16n8k16.row.col.f32.bf16.bf16.f32 "
        "{%0,%1,%2,%3},{%4,%5,%6,%7},{%8,%9},{%0,%1,%2,%3};"
        : "+f"(c[0]), "+f"(c[1]), "+f"(c[2]), "+f"(c[3])
        : "r"(a[0]), "r"(a[1]), "r"(a[2]), "r"(a[3]), "r"(b[0]), "r"(b[1]));
}

// ---------------- split / transpose kernels ----------------
__global__ void split_kernel(const float* __restrict__ src,
                             __nv_bfloat16* __restrict__ hi,
                             __nv_bfloat16* __restrict__ lo, int n4)
{
    int i = blockIdx.x * blockDim.x + threadIdx.x;
    if (i >= n4) return;
    float4 v = ((const float4*)src)[i];
    __nv_bfloat16 h0, h1, h2, h3, l0, l1, l2, l3;
    split_bf16(v.x, h0, l0); split_bf16(v.y, h1, l1);
    split_bf16(v.z, h2, l2); split_bf16(v.w, h3, l3);
    __nv_bfloat162* hp = (__nv_bfloat162*)(hi + (size_t)i * 4);
    __nv_bfloat162* lp = (__nv_bfloat162*)(lo + (size_t)i * 4);
    hp[0] = __nv_bfloat162(h0, h1); hp[1] = __nv_bfloat162(h2, h3);
    lp[0] = __nv_bfloat162(l0, l1); lp[1] = __nv_bfloat162(l2, l3);
}

__global__ void transpose_split_kernel(const float* __restrict__ W,
                                       __nv_bfloat16* __restrict__ hi,
                                       __nv_bfloat16* __restrict__ lo,
                                       int K, int N)
{
    __shared__ float t[32][33];
    const int n0 = blockIdx.x * 32;
    const int k0 = blockIdx.y * 32;
    const int tx = threadIdx.x;
    const int ty = threadIdx.y;
#pragma unroll
    for (int j = 0; j < 32; j += 8)
        t[ty + j][tx] = W[(size_t)(k0 + ty + j) * N + n0 + tx];
    __syncthreads();
#pragma unroll
    for (int j = 0; j < 32; j += 8) {
        float x = t[tx][ty + j];
        __nv_bfloat16 h, l;
        split_bf16(x, h, l);
        size_t o = (size_t)(n0 + ty + j) * K + k0 + tx;
        hi[o] = h;
        lo[o] = l;
    }
}

// ================= bf16-split tensor-core GEMM (ldmatrix fragments) =================
#define BM 128
#define BN 128
#define BK 32
#define SSTRIDE 40
#define TILE_ELEMS (128 * SSTRIDE)
#define STAGE_ELEMS (4 * TILE_ELEMS)
#define GEMM_SMEM_BYTES (2 * STAGE_ELEMS * 2)   // 81920

__global__ __launch_bounds__(256)
void gemm_bf16split_kernel(const __nv_bfloat16* __restrict__ Ahi,
                           const __nv_bfloat16* __restrict__ Alo,
                           const __nv_bfloat16* __restrict__ Bhi,
                           const __nv_bfloat16* __restrict__ Blo,
                           const float* __restrict__ bias, float* __restrict__ C,
                           int M, int N, int K)
{
    extern __shared__ __nv_bfloat16 sm[];
    const int tid = threadIdx.x;
    const int wid = tid >> 5;
    const int lane = tid & 31;
    const int grp = lane >> 2;
    const int qid = lane & 3;
    const int warp_m = wid >> 2;   // 0..1 (64 rows)
    const int warp_n = wid & 3;    // 0..3 (32 cols)

    const int m0 = blockIdx.y * BM;
    const int n0 = blockIdx.x * BN;

    float acc[4][4][4];
#pragma unroll
    for (int i = 0; i < 4; i++)
#pragma unroll
        for (int j = 0; j < 4; j++)
#pragma unroll
            for (int r = 0; r < 4; r++) acc[i][j][r] = 0.f;

    unsigned smem_base = (unsigned)__cvta_generic_to_shared(sm);
    const int NIT = K / BK;

    // ldmatrix per-lane element offsets (within a tile array)
    // A x4: 16 rows x 16 cols at (mt*16, kk*16)
    const unsigned a_elem = (unsigned)((warp_m * 64 + (lane & 15)) * SSTRIDE
                                       + ((lane >> 4) & 1) * 8);
    // B x4: covers 2 n-tiles (16 rows) x 16 cols at (pair*16, kk*16)
    const unsigned b_elem = (unsigned)((warp_n * 32 + ((lane >> 4) & 1) * 8 + (lane & 7)) * SSTRIDE
                                       + ((lane >> 3) & 1) * 8);

    auto load_stage = [&](int stage, int k0) {
        unsigned sbase = smem_base + (unsigned)(stage * STAGE_ELEMS) * 2u;
        const __nv_bfloat16* gsrc[4] = {Ahi, Alo, Bhi, Blo};
        const int gm0[4] = {m0, m0, n0, n0};
#pragma unroll
        for (int arr = 0; arr < 4; arr++) {
            unsigned sa = sbase + (unsigned)(arr * TILE_ELEMS) * 2u;
            const __nv_bfloat16* g = gsrc[arr];
#pragma unroll
            for (int p = 0; p < 2; p++) {
                int i = p * 256 + tid;
                int row = i >> 2;
                int c = i & 3;
                const __nv_bfloat16* src = g + (size_t)(gm0[arr] + row) * K + k0 + c * 8;
                CP_ASYNC16(sa + (unsigned)(row * SSTRIDE + c * 8) * 2u, src);
            }
        }
    };

    load_stage(0, 0);
    CP_COMMIT();

    int stage = 0;
    for (int it = 0; it < NIT; it++) {
        if (it + 1 < NIT) {
            load_stage(stage ^ 1, (it + 1) * BK);
            CP_COMMIT();
            CP_WAIT(1);
        } else {
            CP_WAIT(0);
        }
        __syncthreads();

        const unsigned stg = smem_base + (unsigned)(stage * STAGE_ELEMS) * 2u;
        const unsigned lo_off = (unsigned)TILE_ELEMS * 2u;          // hi->lo
        const unsigned bh_off = (unsigned)(2 * TILE_ELEMS) * 2u;    // base->Bhi

#pragma unroll
        for (int kk = 0; kk < 2; kk++) {
            unsigned ahi[4][4], alo[4][4], bh[2][4], bl[2][4];
#pragma unroll
            for (int mt = 0; mt < 4; mt++) {
                unsigned ad = stg + (a_elem + (unsigned)(mt * 16 * SSTRIDE + kk * 16)) * 2u;
                LDSM_X4(ahi[mt][0], ahi[mt][1], ahi[mt][2], ahi[mt][3], ad);
                LDSM_X4(alo[mt][0], alo[mt][1], alo[mt][2], alo[mt][3], ad + lo_off);
            }
#pragma unroll
            for (int p = 0; p < 2; p++) {
                unsigned bd = stg + bh_off
                            + (b_elem + (unsigned)(p * 16 * SSTRIDE + kk * 16)) * 2u;
                LDSM_X4(bh[p][0], bh[p][1], bh[p][2], bh[p][3], bd);
                LDSM_X4(bl[p][0], bl[p][1], bl[p][2], bl[p][3], bd + lo_off);
            }
            // hi * hi
#pragma unroll
            for (int mt = 0; mt < 4; mt++)
#pragma unroll
                for (int p = 0; p < 2; p++) {
                    mma_bf16(acc[mt][2 * p + 0], ahi[mt], &bh[p][0]);
                    mma_bf16(acc[mt][2 * p + 1], ahi[mt], &bh[p][2]);
                }
            // hi * lo
#pragma unroll
            for (int mt = 0; mt < 4; mt++)
#pragma unroll
                for (int p = 0; p < 2; p++) {
                    mma_bf16(acc[mt][2 * p + 0], ahi[mt], &bl[p][0]);
                    mma_bf16(acc[mt][2 * p + 1], ahi[mt], &bl[p][2]);
                }
            // lo * hi
#pragma unroll
            for (int mt = 0; mt < 4; mt++)
#pragma unroll
                for (int p = 0; p < 2; p++) {
                    mma_bf16(acc[mt][2 * p + 0], alo[mt], &bh[p][0]);
                    mma_bf16(acc[mt][2 * p + 1], alo[mt], &bh[p][2]);
                }
        }
        __syncthreads();
        stage ^= 1;
    }

#pragma unroll
    for (int mt = 0; mt < 4; mt++) {
        const int mrow = m0 + warp_m * 64 + mt * 16 + grp;
#pragma unroll
        for (int nt = 0; nt < 4; nt++) {
            const int col = n0 + warp_n * 32 + nt * 8 + 2 * qid;
            float b0 = bias ? bias[col] : 0.f;
            float b1 = bias ? bias[col + 1] : 0.f;
            float2 v0 = make_float2(acc[mt][nt][0] + b0, acc[mt][nt][1] + b1);
            float2 v1 = make_float2(acc[mt][nt][2] + b0, acc[mt][nt][3] + b1);
            *(float2*)(C + (size_t)mrow * N + col) = v0;
            *(float2*)(C + (size_t)(mrow + 8) * N + col) = v1;
        }
    }
}

// ---------------- fused RoPE + split + relayout ----------------
__global__ void rope_split_kernel(const float* __restrict__ qkv,
                                  const int* __restrict__ positions)
{
    int idx = blockIdx.x * blockDim.x + threadIdx.x;
    if (idx >= MROWS * NHEAD * 64) return;
    const int i = idx & 63;
    const int h = (idx >> 6) & 31;
    const int m = idx >> 11;
    const int b = m >> 11;
    const int s = m & 2047;

    const float pos = (float)positions[m];
    const float inv_freq = powf(10000.0f, -(float)i / 64.0f);
    const float ang = pos * inv_freq;
    const float c = cosf(ang);
    const float sn = sinf(ang);

    const float* row = qkv + (size_t)m * QKV_N + h * HDIM;
    const size_t hb = ((size_t)((b * NHEAD + h) * SLEN) + s) * HDIM;

    {
        float x1 = row[i], x2 = row[i + 64];
        float y1 = x1 * c - x2 * sn;
        float y2 = x2 * c + x1 * sn;
        __nv_bfloat16 h1, l1, h2, l2;
        split_bf16(y1, h1, l1); split_bf16(y2, h2, l2);
        g_q_hi[hb + i] = h1; g_q_hi[hb + i + 64] = h2;
        g_q_lo[hb + i] = l1; g_q_lo[hb + i + 64] = l2;
    }
    {
        float x1 = row[HID + i], x2 = row[HID + i + 64];
        float y1 = x1 * c - x2 * sn;
        float y2 = x2 * c + x1 * sn;
        __nv_bfloat16 h1, l1, h2, l2;
        split_bf16(y1, h1, l1); split_bf16(y2, h2, l2);
        g_k_hi[hb + i] = h1; g_k_hi[hb + i + 64] = h2;
        g_k_lo[hb + i] = l1; g_k_lo[hb + i + 64] = l2;
    }
    {
        float x1 = row[2 * HID + i], x2 = row[2 * HID + i + 64];
        __nv_bfloat16 h1, l1, h2, l2;
        split_bf16(x1, h1, l1); split_bf16(x2, h2, l2);
        g_v_hi[hb + i] = h1; g_v_hi[hb + i + 64] = h2;
        g_v_lo[hb + i] = l1; g_v_lo[hb + i + 64] = l2;
    }
}

// ---------------- tensor-core flash attention (bf16-split, causal) ----------------
#define AQT 128
#define AKT 64
#define QST 136
#define KST 136
#define VST 72
#define SM_QHI 0
#define SM_QLO (SM_QHI + AQT * QST)
#define SM_KHI (SM_QLO + AQT * QST)
#define SM_KLO (SM_KHI + AKT * KST)
#define SM_VHI (SM_KLO + AKT * KST)
#define SM_VLO (SM_VHI + AQT * VST)
#define ATT_SMEM_ELEMS (SM_VLO + AQT * VST)
#define ATT_SMEM_BYTES (ATT_SMEM_ELEMS * 2)   // 141312

__global__ __launch_bounds__(256)
void flash_mma_kernel(const __nv_bfloat16* __restrict__ qh, const __nv_bfloat16* __restrict__ ql,
                      const __nv_bfloat16* __restrict__ kh, const __nv_bfloat16* __restrict__ kl,
                      const __nv_bfloat16* __restrict__ vh, const __nv_bfloat16* __restrict__ vl,
                      float* __restrict__ ctx)
{
    extern __shared__ __nv_bfloat16 sma[];
    const int qt = blockIdx.x;
    const int h  = blockIdx.y;
    const int b  = blockIdx.z;
    const int tid = threadIdx.x;
    const int wid = tid >> 5;
    const int lane = tid & 31;
    const int grp = lane >> 2;
    const int qid = lane & 3;
    const size_t hb = ((size_t)(b * NHEAD + h)) * SLEN * HDIM;
    unsigned sbase = (unsigned)__cvta_generic_to_shared(sma);
    const float scale = 0.08838834764831845f;

    {
        const __nv_bfloat16* g = qh + hb + (size_t)qt * AQT * HDIM;
#pragma unroll
        for (int p = 0; p < 8; p++) {
            int i = p * 256 + tid;
            int row = i >> 4, c = i & 15;
            CP_ASYNC16(sbase + (unsigned)(SM_QHI + row * QST + c * 8) * 2u, g + row * HDIM + c * 8);
        }
        g = ql + hb + (size_t)qt * AQT * HDIM;
#pragma unroll
        for (int p = 0; p < 8; p++) {
            int i = p * 256 + tid;
            int row = i >> 4, c = i & 15;
            CP_ASYNC16(sbase + (unsigned)(SM_QLO + row * QST + c * 8) * 2u, g + row * HDIM + c * 8);
        }
        CP_COMMIT();
    }

    float m0 = -1e30f, m1 = -1e30f, l0 = 0.f, l1 = 0.f;
    float o[16][4];
#pragma unroll
    for (int nt = 0; nt < 16; nt++)
#pragma unroll
        for (int r = 0; r < 4; r++) o[nt][r] = 0.f;

    const int qrow_warp = qt * AQT + wid * 16;
    const int nkt = 2 * qt + 2;

    for (int kt = 0; kt < nkt; kt++) {
        __syncthreads();
        {
            const __nv_bfloat16* g = kh + hb + (size_t)kt * AKT * HDIM;
#pragma unroll
            for (int p = 0; p < 4; p++) {
                int i = p * 256 + tid;
                int row = i >> 4, c = i & 15;
                CP_ASYNC16(sbase + (unsigned)(SM_KHI + row * KST + c * 8) * 2u, g + row * HDIM + c * 8);
            }
            g = kl + hb + (size_t)kt * AKT * HDIM;
#pragma unroll
            for (int p = 0; p < 4; p++) {
                int i = p * 256 + tid;
                int row = i >> 4, c = i & 15;
                CP_ASYNC16(sbase + (unsigned)(SM_KLO + row * KST + c * 8) * 2u, g + row * HDIM + c * 8);
            }
            CP_COMMIT();
        }
        {
            const int kv = tid & 63;
            const int dg = tid >> 6;
            uint4 tv[4];
            const __nv_bfloat16* g = vh + hb + (size_t)(kt * AKT + kv) * HDIM + dg * 32;
#pragma unroll
            for (int c = 0; c < 4; c++) tv[c] = *(const uint4*)(g + c * 8);
            const __nv_bfloat16* tb = (const __nv_bfloat16*)tv;
#pragma unroll
            for (int j = 0; j < 32; j++)
                sma[SM_VHI + (dg * 32 + j) * VST + kv] = tb[j];
            g = vl + hb + (size_t)(kt * AKT + kv) * HDIM + dg * 32;
#pragma unroll
            for (int c = 0; c < 4; c++) tv[c] = *(const uint4*)(g + c * 8);
#pragma unroll
            for (int j = 0; j < 32; j++)
                sma[SM_VLO + (dg * 32 + j) * VST + kv] = tb[j];
        }
        CP_WAIT(0);
        __syncthreads();

        const bool active = (kt * AKT <= qrow_warp + 15);
        if (active) {
            float sreg[8][4];
#pragma unroll
            for (int nt = 0; nt < 8; nt++)
#pragma unroll
                for (int r = 0; r < 4; r++) sreg[nt][r] = 0.f;

#pragma unroll
            for (int d8 = 0; d8 < 8; d8++) {
                const int kof = d8 * 16 + 2 * qid;
                unsigned ahi[4], alo[4];
                {
                    const __nv_bfloat16* p = sma + SM_QHI + (wid * 16 + grp) * QST + kof;
                    ahi[0] = *(const unsigned*)(p);
                    ahi[1] = *(const unsigned*)(p + 8 * QST);
                    ahi[2] = *(const unsigned*)(p + 8);
                    ahi[3] = *(const unsigned*)(p + 8 * QST + 8);
                    const __nv_bfloat16* pl = sma + SM_QLO + (wid * 16 + grp) * QST + kof;
                    alo[0] = *(const unsigned*)(pl);
                    alo[1] = *(const unsigned*)(pl + 8 * QST);
                    alo[2] = *(const unsigned*)(pl + 8);
                    alo[3] = *(const unsigned*)(pl + 8 * QST + 8);
                }
#pragma unroll
                for (int nt = 0; nt < 8; nt++) {
                    unsigned bhi[2], blo[2];
                    const __nv_bfloat16* p = sma + SM_KHI + (nt * 8 + grp) * KST + kof;
                    bhi[0] = *(const unsigned*)(p);
                    bhi[1] = *(const unsigned*)(p + 8);
                    const __nv_bfloat16* pl = sma + SM_KLO + (nt * 8 + grp) * KST + kof;
                    blo[0] = *(const unsigned*)(pl);
                    blo[1] = *(const unsigned*)(pl + 8);
                    mma_bf16(sreg[nt], ahi, bhi);
                    mma_bf16(sreg[nt], ahi, blo);
                    mma_bf16(sreg[nt], alo, bhi);
                }
            }

            const int row0 = qrow_warp + grp;
            const int row1 = row0 + 8;
#pragma unroll
            for (int nt = 0; nt < 8; nt++) {
                const int c0 = kt * AKT + nt * 8 + 2 * qid;
                const int c1 = c0 + 1;
                sreg[nt][0] = (c0 <= row0) ? sreg[nt][0] * scale : -1e30f;
                sreg[nt][1] = (c1 <= row0) ? sreg[nt][1] * scale : -1e30f;
                sreg[nt][2] = (c0 <= row1) ? sreg[nt][2] * scale : -1e30f;
                sreg[nt][3] = (c1 <= row1) ? sreg[nt][3] * scale : -1e30f;
            }

            float tm0 = -1e30f, tm1 = -1e30f;
#pragma unroll
            for (int nt = 0; nt < 8; nt++) {
                tm0 = fmaxf(tm0, fmaxf(sreg[nt][0], sreg[nt][1]));
                tm1 = fmaxf(tm1, fmaxf(sreg[nt][2], sreg[nt][3]));
            }
            tm0 = fmaxf(tm0, __shfl_xor_sync(0xffffffffu, tm0, 1));
            tm0 = fmaxf(tm0, __shfl_xor_sync(0xffffffffu, tm0, 2));
            tm1 = fmaxf(tm1, __shfl_xor_sync(0xffffffffu, tm1, 1));
            tm1 = fmaxf(tm1, __shfl_xor_sync(0xffffffffu, tm1, 2));
            const float mn0 = fmaxf(m0, tm0);
            const float mn1 = fmaxf(m1, tm1);
            const float al0 = __expf(m0 - mn0);
            const float al1 = __expf(m1 - mn1);
            m0 = mn0; m1 = mn1;
            float ps0 = 0.f, ps1 = 0.f;
#pragma unroll
            for (int nt = 0; nt < 8; nt++) {
                sreg[nt][0] = __expf(sreg[nt][0] - m0);
                sreg[nt][1] = __expf(sreg[nt][1] - m0);
                sreg[nt][2] = __expf(sreg[nt][2] - m1);
                sreg[nt][3] = __expf(sreg[nt][3] - m1);
                ps0 += sreg[nt][0] + sreg[nt][1];
                ps1 += sreg[nt][2] + sreg[nt][3];
            }
            l0 = l0 * al0 + ps0;
            l1 = l1 * al1 + ps1;
#pragma unroll
            for (int nt = 0; nt < 16; nt++) {
                o[nt][0] *= al0; o[nt][1] *= al0;
                o[nt][2] *= al1; o[nt][3] *= al1;
            }

#pragma unroll
            for (int c = 0; c < 4; c++) {
                unsigned phi[4], plo[4];
#pragma unroll
                for (int half = 0; half < 2; half++) {
                    const float x0 = sreg[2 * c + half][0];
                    const float x1 = sreg[2 * c + half][1];
                    const float x2 = sreg[2 * c + half][2];
                    const float x3 = sreg[2 * c + half][3];
                    __nv_bfloat16 h0 = __float2bfloat16(x0);
                    __nv_bfloat16 h1 = __float2bfloat16(x1);
                    __nv_bfloat16 h2 = __float2bfloat16(x2);
                    __nv_bfloat16 h3 = __float2bfloat16(x3);
                    phi[0 + 2 * half] = pack_bf16x2(__bfloat162float(h0), __bfloat162float(h1));
                    phi[1 + 2 * half] = pack_bf16x2(__bfloat162float(h2), __bfloat162float(h3));
                    plo[0 + 2 * half] = pack_bf16x2(x0 - __bfloat162float(h0), x1 - __bfloat162float(h1));
                    plo[1 + 2 * half] = pack_bf16x2(x2 - __bfloat162float(h2), x3 - __bfloat162float(h3));
                }
                const int kof = 2 * qid + 16 * c;
#pragma unroll
                for (int nt = 0; nt < 16; nt++) {
                    unsigned bhi[2], blo[2];
                    const __nv_bfloat16* p = sma + SM_VHI + (nt * 8 + grp) * VST + kof;
                    bhi[0] = *(const unsigned*)(p);
                    bhi[1] = *(const unsigned*)(p + 8);
                    const __nv_bfloat16* pl = sma + SM_VLO + (nt * 8 + grp) * VST + kof;
                    blo[0] = *(const unsigned*)(pl);
                    blo[1] = *(const unsigned*)(pl + 8);
                    mma_bf16(o[nt], phi, bhi);
                    mma_bf16(o[nt], plo, bhi);
                    mma_bf16(o[nt], phi, blo);
                }
            }
        }
    }

    l0 += __shfl_xor_sync(0xffffffffu, l0, 1);
    l0 += __shfl_xor_sync(0xffffffffu, l0, 2);
    l1 += __shfl_xor_sync(0xffffffffu, l1, 1);
    l1 += __shfl_xor_sync(0xffffffffu, l1, 2);
    const float inv0 = 1.0f / l0;
    const float inv1 = 1.0f / l1;

    const int row0 = b * SLEN + qt * AQT + wid * 16 + grp;
#pragma unroll
    for (int nt = 0; nt < 16; nt++) {
        const int col = h * HDIM + nt * 8 + 2 * qid;
        *(float2*)(ctx + (size_t)row0 * HID + col) =
            make_float2(o[nt][0] * inv0, o[nt][1] * inv0);
        *(float2*)(ctx + (size_t)(row0 + 8) * HID + col) =
            make_float2(o[nt][2] * inv1, o[nt][3] * inv1);
    }
}

// ---------------- launch ----------------
extern "C" void kernel_launch(void* const* d_in, const int* in_sizes, int n_in,
                              void* d_out, int out_size)
{
    const float* hs    = (const float*)d_in[0];
    const int*   pos   = (const int*)d_in[1];
    const float* Wqkv  = (const float*)d_in[2];
    const float* bqkv  = (const float*)d_in[3];
    const float* Wo    = (const float*)d_in[4];
    float* out = (float*)d_out;

    float *qkv, *ctx;
    __nv_bfloat16 *hs_hi, *hs_lo, *ctx_hi, *ctx_lo, *wqkv_hi, *wqkv_lo, *wo_hi, *wo_lo;
    __nv_bfloat16 *q_hi, *q_lo, *k_hi, *k_lo, *v_hi, *v_lo;
    cudaGetSymbolAddress((void**)&qkv, g_qkv);
    cudaGetSymbolAddress((void**)&ctx, g_ctx);
    cudaGetSymbolAddress((void**)&hs_hi, g_hs_hi);
    cudaGetSymbolAddress((void**)&hs_lo, g_hs_lo);
    cudaGetSymbolAddress((void**)&ctx_hi, g_ctx_hi);
    cudaGetSymbolAddress((void**)&ctx_lo, g_ctx_lo);
    cudaGetSymbolAddress((void**)&wqkv_hi, g_wqkv_hi);
    cudaGetSymbolAddress((void**)&wqkv_lo, g_wqkv_lo);
    cudaGetSymbolAddress((void**)&wo_hi, g_wo_hi);
    cudaGetSymbolAddress((void**)&wo_lo, g_wo_lo);
    cudaGetSymbolAddress((void**)&q_hi, g_q_hi);
    cudaGetSymbolAddress((void**)&q_lo, g_q_lo);
    cudaGetSymbolAddress((void**)&k_hi, g_k_hi);
    cudaGetSymbolAddress((void**)&k_lo, g_k_lo);
    cudaGetSymbolAddress((void**)&v_hi, g_v_hi);
    cudaGetSymbolAddress((void**)&v_lo, g_v_lo);

    static int configured = 0;
    if (!configured) {
        cudaFuncSetAttribute(gemm_bf16split_kernel,
                             cudaFuncAttributeMaxDynamicSharedMemorySize, GEMM_SMEM_BYTES);
        cudaFuncSetAttribute(flash_mma_kernel,
                             cudaFuncAttributeMaxDynamicSharedMemorySize, ATT_SMEM_BYTES);
        configured = 1;
    }

    // 0) splits + weight transposes
    {
        int n4 = MROWS * HID / 4;
        split_kernel<<<(n4 + 255) / 256, 256>>>(hs, hs_hi, hs_lo, n4);
        dim3 g1(QKV_N / 32, HID / 32);
        transpose_split_kernel<<<g1, dim3(32, 8)>>>(Wqkv, wqkv_hi, wqkv_lo, HID, QKV_N);
        dim3 g2(HID / 32, HID / 32);
        transpose_split_kernel<<<g2, dim3(32, 8)>>>(Wo, wo_hi, wo_lo, HID, HID);
    }
    // 1) qkv = hs @ W_qkv + b
    {
        dim3 grid(QKV_N / BN, MROWS / BM);   // (96, 32)
        gemm_bf16split_kernel<<<grid, 256, GEMM_SMEM_BYTES>>>(
            hs_hi, hs_lo, wqkv_hi, wqkv_lo, bqkv, qkv, MROWS, QKV_N, HID);
    }
    // 2) RoPE + split + relayout
    {
        int total = MROWS * NHEAD * 64;
        rope_split_kernel<<<(total + 255) / 256, 256>>>(qkv, pos);
    }
    // 3) flash attention -> ctx (fp32)
    {
        dim3 grid(SLEN / AQT, NHEAD, BATCH);   // (16, 32, 2)
        flash_mma_kernel<<<grid, 256, ATT_SMEM_BYTES>>>(q_hi, q_lo, k_hi, k_lo,
                                                        v_hi, v_lo, ctx);
    }
    // 3b) split ctx for O GEMM
    {
        int n4 = MROWS * HID / 4;
        split_kernel<<<(n4 + 255) / 256, 256>>>(ctx, ctx_hi, ctx_lo, n4);
    }
    // 4) out = ctx @ W_o
    {
        dim3 grid(HID / BN, MROWS / BM);     // (32, 32)
        gemm_bf16split_kernel<<<grid, 256, GEMM_SMEM_BYTES>>>(
            ctx_hi, ctx_lo, wo_hi, wo_lo, nullptr, out, MROWS, HID, HID);
    }
}